// round 1
// baseline (speedup 1.0000x reference)
#include <cuda_runtime.h>
#include <math.h>

// Shapes (fixed by the problem)
#define Bq 4
#define Nq 2048
#define Eq 768
#define Hq 12
#define Mq 256
#define Dhq 64
#define Fq 3072
#define ROWS (Bq*Hq*Nq)   // 98304
#define BN (Bq*Nq)        // 8192

#define RATIO 0.0625f            // M^-0.5
#define REPS  6.25e-6f           // RATIO * EPS(1e-4)
#define XSCL  0.35355339059327373f  // Dh^-0.25

// Scratch (device globals; allocation-free)
__device__ float g_h[ROWS*Dhq];      // LN1 out, head layout [B,H,N,Dh]
__device__ float g_u[ROWS*Mq];       // u, then e = exp(u - diag - stabq)
__device__ float g_diag[ROWS];
__device__ float g_stabq[ROWS];
__device__ float g_scale[ROWS];      // 0.0625*exp(stabq - stabk)
__device__ float g_stabk[Bq*Hq];
__device__ float g_ctx[Bq*Hq*Mq*Dhq];
__device__ float g_ksum[Bq*Hq*Mq];
__device__ float g_x1[BN*Eq];        // x + attn
__device__ float g_h2[BN*Eq];        // LN2 out
__device__ float g_mid[BN*Fq];       // gelu(h2@W1+b1)

// ---------------- LN1: per-token layernorm + head-layout write + diag ----------------
__global__ void k_ln1(const float* __restrict__ x, const float* __restrict__ g,
                      const float* __restrict__ b) {
    int row = blockIdx.x;           // 0..8191
    int tid = threadIdx.x;          // 768 threads
    float v = x[row*Eq + tid];
    __shared__ float red[48];
    __shared__ float mv[2];
    float s1 = v, s2 = v*v;
    #pragma unroll
    for (int o=16;o;o>>=1){ s1+=__shfl_xor_sync(~0u,s1,o); s2+=__shfl_xor_sync(~0u,s2,o); }
    int w = tid>>5, l = tid&31;
    if (l==0){ red[w]=s1; red[24+w]=s2; }
    __syncthreads();
    if (tid<32){
        float a = tid<24 ? red[tid]    : 0.f;
        float c = tid<24 ? red[24+tid] : 0.f;
        #pragma unroll
        for (int o=16;o;o>>=1){ a+=__shfl_xor_sync(~0u,a,o); c+=__shfl_xor_sync(~0u,c,o); }
        if (tid==0){ float m=a*(1.f/Eq); mv[0]=m; mv[1]=rsqrtf(c*(1.f/Eq)-m*m+1e-5f); }
    }
    __syncthreads();
    float y = (v - mv[0]) * mv[1] * g[tid] + b[tid];
    int bb = row>>11, n = row&2047, hd = tid>>6, d = tid&63;
    g_h[((bb*Hq+hd)*Nq + n)*Dhq + d] = y;
    // per-head diag = 0.5 * s^2 * sum(y^2) = 0.0625 * sum(y^2)
    __shared__ float sdg[Hq];
    if (tid < Hq) sdg[tid] = 0.f;
    __syncthreads();
    float yy = y*y;
    #pragma unroll
    for (int o=16;o;o>>=1) yy += __shfl_xor_sync(~0u,yy,o);
    if (l==0) atomicAdd(&sdg[w>>1], yy);
    __syncthreads();
    if (tid < Hq) g_diag[(bb*Hq+tid)*Nq + n] = 0.0625f * sdg[tid];
}

// ---------------- LN2: plain row-major out ----------------
__global__ void k_ln2(const float* __restrict__ g, const float* __restrict__ b) {
    int row = blockIdx.x;
    int tid = threadIdx.x;
    float v = g_x1[row*Eq + tid];
    __shared__ float red[48];
    __shared__ float mv[2];
    float s1 = v, s2 = v*v;
    #pragma unroll
    for (int o=16;o;o>>=1){ s1+=__shfl_xor_sync(~0u,s1,o); s2+=__shfl_xor_sync(~0u,s2,o); }
    int w = tid>>5, l = tid&31;
    if (l==0){ red[w]=s1; red[24+w]=s2; }
    __syncthreads();
    if (tid<32){
        float a = tid<24 ? red[tid]    : 0.f;
        float c = tid<24 ? red[24+tid] : 0.f;
        #pragma unroll
        for (int o=16;o;o>>=1){ a+=__shfl_xor_sync(~0u,a,o); c+=__shfl_xor_sync(~0u,c,o); }
        if (tid==0){ float m=a*(1.f/Eq); mv[0]=m; mv[1]=rsqrtf(c*(1.f/Eq)-m*m+1e-5f); }
    }
    __syncthreads();
    g_h2[row*Eq + tid] = (v - mv[0]) * mv[1] * g[tid] + b[tid];
}

// ---------------- u = (s*h) @ proj^T : [98304 x 64] @ [64 x 256] ----------------
__global__ void k_ugemm(const float* __restrict__ proj) {
    __shared__ float as[32][128];
    __shared__ float bs[32][128];
    int tid = threadIdx.x, tx = tid&15, ty = tid>>4;
    int rbase = blockIdx.y*128, mbase = blockIdx.x*128;
    float acc[8][8] = {};
    for (int kt=0; kt<64; kt+=32) {
        #pragma unroll
        for (int t=0;t<4;t++){
            int q = tid + t*256; int row = q>>3, c = q&7;
            float4 v = *(const float4*)&g_h[(rbase+row)*64 + kt + c*4];
            as[c*4+0][row]=v.x*XSCL; as[c*4+1][row]=v.y*XSCL;
            as[c*4+2][row]=v.z*XSCL; as[c*4+3][row]=v.w*XSCL;
            float4 p = *(const float4*)&proj[(mbase+row)*64 + kt + c*4];
            bs[c*4+0][row]=p.x; bs[c*4+1][row]=p.y; bs[c*4+2][row]=p.z; bs[c*4+3][row]=p.w;
        }
        __syncthreads();
        #pragma unroll
        for (int k=0;k<32;k++){
            float a[8], bv[8];
            #pragma unroll
            for (int i=0;i<8;i++) a[i]=as[k][ty*8+i];
            #pragma unroll
            for (int j=0;j<8;j++) bv[j]=bs[k][tx*8+j];
            #pragma unroll
            for (int i=0;i<8;i++)
                #pragma unroll
                for (int j=0;j<8;j++) acc[i][j]=fmaf(a[i],bv[j],acc[i][j]);
        }
        __syncthreads();
    }
    #pragma unroll
    for (int i=0;i<8;i++)
        #pragma unroll
        for (int j=0;j<8;j++)
            g_u[(rbase+ty*8+i)*256 + mbase+tx*8+j] = acc[i][j];
}

// ---------------- row max (stab_q) ----------------
__global__ void k_stabq() {
    int row = blockIdx.x*8 + (threadIdx.x>>5);
    int l = threadIdx.x & 31;
    const float* u = g_u + (size_t)row*256;
    float m = -1e30f;
    #pragma unroll
    for (int j=0;j<8;j++) m = fmaxf(m, u[l + j*32]);
    #pragma unroll
    for (int o=16;o;o>>=1) m = fmaxf(m, __shfl_xor_sync(~0u,m,o));
    if (l==0) g_stabq[row] = m;
}

// ---------------- per-head max (stab_k) ----------------
__global__ void k_stabk() {
    int g = blockIdx.x, tid = threadIdx.x;
    __shared__ float red[8];
    float m = -1e30f;
    #pragma unroll
    for (int j=0;j<8;j++) m = fmaxf(m, g_stabq[g*2048 + tid + j*256]);
    #pragma unroll
    for (int o=16;o;o>>=1) m = fmaxf(m, __shfl_xor_sync(~0u,m,o));
    if ((tid&31)==0) red[tid>>5] = m;
    __syncthreads();
    if (tid==0){
        float t = red[0];
        #pragma unroll
        for (int i=1;i<8;i++) t = fmaxf(t, red[i]);
        g_stabk[g] = t;
    }
}

// ---------------- e = exp(u - diag - stabq), in place ----------------
__global__ void k_exp() {
    int idx = blockIdx.x*blockDim.x + threadIdx.x;   // 25,165,824 total
    int r = idx >> 8;
    g_u[idx] = __expf(g_u[idx] - g_diag[r] - g_stabq[r]);
}

__global__ void k_scale() {
    int r = blockIdx.x*256 + threadIdx.x;
    g_scale[r] = RATIO * __expf(g_stabq[r] - g_stabk[r>>11]);
}

// ---------------- ctx[g] = kp^T @ h : [256 x 2048] @ [2048 x 64] per head ----------------
__global__ void k_ctx() {
    __shared__ float es[32][128];
    __shared__ float hs[32][64];
    int tid = threadIdx.x, tx = tid&15, ty = tid>>4;
    int g = blockIdx.y, mbase = blockIdx.x*128;
    size_t ebase = (size_t)g*2048*256;
    const float* hb = g_h + g*2048*64;
    float acc[8][4] = {};
    for (int n0=0; n0<2048; n0+=32) {
        #pragma unroll
        for (int t=0;t<4;t++){
            int q = tid + t*256; int kk = q>>5, mq = q&31;
            float sc = g_scale[g*2048 + n0 + kk];
            float4 v = *(const float4*)&g_u[ebase + (size_t)(n0+kk)*256 + mbase + mq*4];
            es[kk][mq*4+0]=fmaf(v.x,sc,REPS); es[kk][mq*4+1]=fmaf(v.y,sc,REPS);
            es[kk][mq*4+2]=fmaf(v.z,sc,REPS); es[kk][mq*4+3]=fmaf(v.w,sc,REPS);
        }
        #pragma unroll
        for (int t=0;t<2;t++){
            int q = tid + t*256; int kk = q>>4, dq = q&15;
            *(float4*)&hs[kk][dq*4] = *(const float4*)&hb[(n0+kk)*64 + dq*4];
        }
        __syncthreads();
        #pragma unroll
        for (int k=0;k<32;k++){
            float a[8], bv[4];
            #pragma unroll
            for (int i=0;i<8;i++) a[i]=es[k][ty*8+i];
            #pragma unroll
            for (int j=0;j<4;j++) bv[j]=hs[k][tx*4+j];
            #pragma unroll
            for (int i=0;i<8;i++)
                #pragma unroll
                for (int j=0;j<4;j++) acc[i][j]=fmaf(a[i],bv[j],acc[i][j]);
        }
        __syncthreads();
    }
    #pragma unroll
    for (int i=0;i<8;i++)
        #pragma unroll
        for (int j=0;j<4;j++)
            g_ctx[(g*256 + mbase + ty*8+i)*64 + tx*4+j] = acc[i][j];
}

// ---------------- ksum ----------------
__global__ void k_ksum_init() {
    g_ksum[blockIdx.x*256 + threadIdx.x] = 2048.f * REPS;
}
__global__ void k_ksum() {
    int g = blockIdx.x, nc = blockIdx.y, m = threadIdx.x;
    __shared__ float sc[256];
    sc[m] = g_scale[g*2048 + nc*256 + m];
    __syncthreads();
    const float* e = g_u + ((size_t)(g*2048 + nc*256))*256 + m;
    float acc = 0.f;
    #pragma unroll 4
    for (int n=0; n<256; n++) acc = fmaf(e[(size_t)n*256], sc[n], acc);
    atomicAdd(&g_ksum[g*256 + m], acc);
}

// ---------------- attn = (qp @ ctx) / (qp . ksum); x1 = x + attn ----------------
__global__ void k_attn(const float* __restrict__ x) {
    __shared__ float qs[32][128];
    __shared__ float cs[32][64];
    __shared__ float ks[32];
    __shared__ float sden[128];
    int tid = threadIdx.x, tx = tid&15, ty = tid>>4;
    int g = blockIdx.y, nbase = blockIdx.x*128;
    size_t ebase = (size_t)g*2048*256;
    float acc[8][4] = {}, den[8] = {};
    for (int m0=0; m0<256; m0+=32) {
        #pragma unroll
        for (int t=0;t<4;t++){
            int q = tid + t*256; int nn = q>>3, cq = q&7;
            float4 v = *(const float4*)&g_u[ebase + (size_t)(nbase+nn)*256 + m0 + cq*4];
            qs[cq*4+0][nn]=fmaf(v.x,RATIO,REPS); qs[cq*4+1][nn]=fmaf(v.y,RATIO,REPS);
            qs[cq*4+2][nn]=fmaf(v.z,RATIO,REPS); qs[cq*4+3][nn]=fmaf(v.w,RATIO,REPS);
        }
        #pragma unroll
        for (int t=0;t<2;t++){
            int q = tid + t*256; int kk = q>>4, dq = q&15;
            *(float4*)&cs[kk][dq*4] = *(const float4*)&g_ctx[(g*256 + m0 + kk)*64 + dq*4];
        }
        if (tid < 32) ks[tid] = g_ksum[g*256 + m0 + tid];
        __syncthreads();
        #pragma unroll
        for (int k=0;k<32;k++){
            float a[8], bv[4];
            #pragma unroll
            for (int i=0;i<8;i++) a[i]=qs[k][ty*8+i];
            #pragma unroll
            for (int j=0;j<4;j++) bv[j]=cs[k][tx*4+j];
            #pragma unroll
            for (int i=0;i<8;i++)
                #pragma unroll
                for (int j=0;j<4;j++) acc[i][j]=fmaf(a[i],bv[j],acc[i][j]);
            if (tx==0){
                #pragma unroll
                for (int i=0;i<8;i++) den[i]=fmaf(a[i],ks[k],den[i]);
            }
        }
        __syncthreads();
    }
    if (tx==0){
        #pragma unroll
        for (int i=0;i<8;i++) sden[ty*8+i] = den[i];
    }
    __syncthreads();
    int bb = g/12, hd = g%12;
    #pragma unroll
    for (int i=0;i<8;i++){
        float dinv = 1.f / sden[ty*8+i];
        int n = nbase + ty*8 + i;
        #pragma unroll
        for (int j=0;j<4;j++){
            size_t xi = ((size_t)(bb*2048 + n))*768 + hd*64 + tx*4 + j;
            g_x1[xi] = x[xi] + acc[i][j]*dinv;
        }
    }
}

// ---------------- MLP GEMM1 + bias + exact GELU ----------------
__global__ void k_mlp1(const float* __restrict__ W1, const float* __restrict__ b1) {
    __shared__ float as[16][128];
    __shared__ float bs[16][128];
    int tid = threadIdx.x, tx = tid&15, ty = tid>>4;
    int cbase = blockIdx.x*128, rbase = blockIdx.y*128;
    float acc[8][8] = {};
    for (int kt=0; kt<768; kt+=16) {
        #pragma unroll
        for (int t=0;t<2;t++){
            int q = tid + t*256; int row = q>>2, c = q&3;
            float4 v = *(const float4*)&g_h2[(size_t)(rbase+row)*768 + kt + c*4];
            as[c*4+0][row]=v.x; as[c*4+1][row]=v.y; as[c*4+2][row]=v.z; as[c*4+3][row]=v.w;
        }
        #pragma unroll
        for (int t=0;t<2;t++){
            int q = tid + t*256; int kk = q>>5, cq = q&31;
            *(float4*)&bs[kk][cq*4] = *(const float4*)&W1[(size_t)(kt+kk)*3072 + cbase + cq*4];
        }
        __syncthreads();
        #pragma unroll
        for (int k=0;k<16;k++){
            float a[8], bv[8];
            #pragma unroll
            for (int i=0;i<8;i++) a[i]=as[k][ty*8+i];
            #pragma unroll
            for (int j=0;j<8;j++) bv[j]=bs[k][tx*8+j];
            #pragma unroll
            for (int i=0;i<8;i++)
                #pragma unroll
                for (int j=0;j<8;j++) acc[i][j]=fmaf(a[i],bv[j],acc[i][j]);
        }
        __syncthreads();
    }
    #pragma unroll
    for (int i=0;i<8;i++)
        #pragma unroll
        for (int j=0;j<8;j++){
            float v = acc[i][j] + b1[cbase + tx*8 + j];
            v = 0.5f * v * (1.f + erff(v * 0.70710678118654752f));
            g_mid[(size_t)(rbase+ty*8+i)*3072 + cbase + tx*8 + j] = v;
        }
}

// ---------------- MLP GEMM2 + bias + residual -> out ----------------
__global__ void k_mlp2(const float* __restrict__ W2, const float* __restrict__ b2,
                       float* __restrict__ out) {
    __shared__ float as[16][128];
    __shared__ float bs[16][128];
    int tid = threadIdx.x, tx = tid&15, ty = tid>>4;
    int cbase = blockIdx.x*128, rbase = blockIdx.y*128;
    float acc[8][8] = {};
    for (int kt=0; kt<3072; kt+=16) {
        #pragma unroll
        for (int t=0;t<2;t++){
            int q = tid + t*256; int row = q>>2, c = q&3;
            float4 v = *(const float4*)&g_mid[(size_t)(rbase+row)*3072 + kt + c*4];
            as[c*4+0][row]=v.x; as[c*4+1][row]=v.y; as[c*4+2][row]=v.z; as[c*4+3][row]=v.w;
        }
        #pragma unroll
        for (int t=0;t<2;t++){
            int q = tid + t*256; int kk = q>>5, cq = q&31;
            *(float4*)&bs[kk][cq*4] = *(const float4*)&W2[(size_t)(kt+kk)*768 + cbase + cq*4];
        }
        __syncthreads();
        #pragma unroll
        for (int k=0;k<16;k++){
            float a[8], bv[8];
            #pragma unroll
            for (int i=0;i<8;i++) a[i]=as[k][ty*8+i];
            #pragma unroll
            for (int j=0;j<8;j++) bv[j]=bs[k][tx*8+j];
            #pragma unroll
            for (int i=0;i<8;i++)
                #pragma unroll
                for (int j=0;j<8;j++) acc[i][j]=fmaf(a[i],bv[j],acc[i][j]);
        }
        __syncthreads();
    }
    #pragma unroll
    for (int i=0;i<8;i++)
        #pragma unroll
        for (int j=0;j<8;j++){
            size_t idx = (size_t)(rbase+ty*8+i)*768 + cbase + tx*8 + j;
            out[idx] = acc[i][j] + b2[cbase + tx*8 + j] + g_x1[idx];
        }
}

extern "C" void kernel_launch(void* const* d_in, const int* in_sizes, int n_in,
                              void* d_out, int out_size) {
    const float* x    = (const float*)d_in[0];
    const float* proj = (const float*)d_in[1];
    const float* ln1g = (const float*)d_in[2];
    const float* ln1b = (const float*)d_in[3];
    const float* ln2g = (const float*)d_in[4];
    const float* ln2b = (const float*)d_in[5];
    const float* W1   = (const float*)d_in[6];
    const float* b1   = (const float*)d_in[7];
    const float* W2   = (const float*)d_in[8];
    const float* b2   = (const float*)d_in[9];
    float* out = (float*)d_out;

    k_ln1<<<BN, Eq>>>(x, ln1g, ln1b);
    k_ugemm<<<dim3(2, ROWS/128), 256>>>(proj);
    k_stabq<<<ROWS/8, 256>>>();
    k_stabk<<<Bq*Hq, 256>>>();
    k_exp<<<(ROWS*Mq)/512, 512>>>();
    k_scale<<<ROWS/256, 256>>>();
    k_ksum_init<<<Bq*Hq, 256>>>();
    k_ctx<<<dim3(2, Bq*Hq), 256>>>();
    k_ksum<<<dim3(Bq*Hq, 8), 256>>>();
    k_attn<<<dim3(Nq/128, Bq*Hq), 256>>>(x);
    k_ln2<<<BN, Eq>>>(ln2g, ln2b);
    k_mlp1<<<dim3(Fq/128, BN/128), 256>>>(W1, b1);
    k_mlp2<<<dim3(Eq/128, BN/128), 256>>>(W2, b2, out);
}

// round 3
// speedup vs baseline: 2.0898x; 2.0898x over previous
#include <cuda_runtime.h>
#include <math.h>
#include <stdint.h>

// Shapes (fixed by the problem)
#define Bq 4
#define Nq 2048
#define Eq 768
#define Hq 12
#define Mq 256
#define Dhq 64
#define Fq 3072
#define ROWS (Bq*Hq*Nq)   // 98304
#define BN (Bq*Nq)        // 8192

#define RATIO 0.0625f            // M^-0.5
#define REPS  6.25e-6f           // RATIO * EPS(1e-4)
#define XSCL  0.35355339059327373f  // Dh^-0.25

// Scratch (device globals; allocation-free)
__device__ float g_h[ROWS*Dhq];      // LN1 out, head layout [B,H,N,Dh]
__device__ float g_u[ROWS*Mq];       // u, then e = exp(u - diag - stabq)
__device__ float g_diag[ROWS];
__device__ float g_stabq[ROWS];
__device__ float g_scale[ROWS];      // 0.0625*exp(stabq - stabk)
__device__ float g_stabk[Bq*Hq];
__device__ float g_ctx[Bq*Hq*Mq*Dhq];
__device__ float g_ksum[Bq*Hq*Mq];
__device__ float g_x1[BN*Eq];        // x + attn
__device__ float g_h2[BN*Eq];        // LN2 out (tf32-rounded)
__device__ float g_mid[BN*Fq];       // gelu(h2@W1+b1) (tf32-rounded)
__device__ float g_w1t[Fq*Eq];       // W1^T [3072 x 768], tf32-rounded
__device__ float g_w2t[Eq*Fq];       // W2^T [768 x 3072], tf32-rounded

// ======================= helpers =======================
__device__ __forceinline__ uint32_t s2u(const void* p){
    uint32_t a;
    asm("{ .reg .u64 t; cvta.to.shared.u64 t, %1; cvt.u32.u64 %0, t; }":"=r"(a):"l"(p));
    return a;
}
__device__ __forceinline__ float tf32r(float x){
    float y; asm("cvt.rna.tf32.f32 %0, %1;":"=f"(y):"f"(x)); return y;
}
__device__ __forceinline__ void cpasync16(uint32_t sa, const void* ga){
    asm volatile("cp.async.cg.shared.global [%0], [%1], 16;" :: "r"(sa), "l"(ga));
}
// warp-level tf32 MMA (sm_80 baseline; valid on plain sm_103 target)
__device__ __forceinline__ void mma8(float* d, const float* a, const float* b){
    asm volatile("mma.sync.aligned.m16n8k8.row.col.f32.tf32.tf32.f32 "
        "{%0,%1,%2,%3}, {%4,%5,%6,%7}, {%8,%9}, {%0,%1,%2,%3};"
        : "+f"(d[0]),"+f"(d[1]),"+f"(d[2]),"+f"(d[3])
        : "r"(__float_as_uint(a[0])),"r"(__float_as_uint(a[1])),
          "r"(__float_as_uint(a[2])),"r"(__float_as_uint(a[3])),
          "r"(__float_as_uint(b[0])),"r"(__float_as_uint(b[1])));
}

// ---------------- LN1: per-token layernorm + head-layout write + diag ----------------
__global__ void k_ln1(const float* __restrict__ x, const float* __restrict__ g,
                      const float* __restrict__ b) {
    int row = blockIdx.x;           // 0..8191
    int tid = threadIdx.x;          // 768 threads
    float v = x[row*Eq + tid];
    __shared__ float red[48];
    __shared__ float mv[2];
    float s1 = v, s2 = v*v;
    #pragma unroll
    for (int o=16;o;o>>=1){ s1+=__shfl_xor_sync(~0u,s1,o); s2+=__shfl_xor_sync(~0u,s2,o); }
    int w = tid>>5, l = tid&31;
    if (l==0){ red[w]=s1; red[24+w]=s2; }
    __syncthreads();
    if (tid<32){
        float a = tid<24 ? red[tid]    : 0.f;
        float c = tid<24 ? red[24+tid] : 0.f;
        #pragma unroll
        for (int o=16;o;o>>=1){ a+=__shfl_xor_sync(~0u,a,o); c+=__shfl_xor_sync(~0u,c,o); }
        if (tid==0){ float m=a*(1.f/Eq); mv[0]=m; mv[1]=rsqrtf(c*(1.f/Eq)-m*m+1e-5f); }
    }
    __syncthreads();
    float y = (v - mv[0]) * mv[1] * g[tid] + b[tid];
    int bb = row>>11, n = row&2047, hd = tid>>6, d = tid&63;
    g_h[((bb*Hq+hd)*Nq + n)*Dhq + d] = y;
    __shared__ float sdg[Hq];
    if (tid < Hq) sdg[tid] = 0.f;
    __syncthreads();
    float yy = y*y;
    #pragma unroll
    for (int o=16;o;o>>=1) yy += __shfl_xor_sync(~0u,yy,o);
    if (l==0) atomicAdd(&sdg[w>>1], yy);
    __syncthreads();
    if (tid < Hq) g_diag[(bb*Hq+tid)*Nq + n] = 0.0625f * sdg[tid];
}

// ---------------- LN2: plain row-major out (tf32-rounded for MMA) ----------------
__global__ void k_ln2(const float* __restrict__ g, const float* __restrict__ b) {
    int row = blockIdx.x;
    int tid = threadIdx.x;
    float v = g_x1[row*Eq + tid];
    __shared__ float red[48];
    __shared__ float mv[2];
    float s1 = v, s2 = v*v;
    #pragma unroll
    for (int o=16;o;o>>=1){ s1+=__shfl_xor_sync(~0u,s1,o); s2+=__shfl_xor_sync(~0u,s2,o); }
    int w = tid>>5, l = tid&31;
    if (l==0){ red[w]=s1; red[24+w]=s2; }
    __syncthreads();
    if (tid<32){
        float a = tid<24 ? red[tid]    : 0.f;
        float c = tid<24 ? red[24+tid] : 0.f;
        #pragma unroll
        for (int o=16;o;o>>=1){ a+=__shfl_xor_sync(~0u,a,o); c+=__shfl_xor_sync(~0u,c,o); }
        if (tid==0){ float m=a*(1.f/Eq); mv[0]=m; mv[1]=rsqrtf(c*(1.f/Eq)-m*m+1e-5f); }
    }
    __syncthreads();
    g_h2[row*Eq + tid] = tf32r((v - mv[0]) * mv[1] * g[tid] + b[tid]);
}

// ---------------- u = (s*h) @ proj^T : [98304 x 64] @ [64 x 256] ----------------
__global__ void k_ugemm(const float* __restrict__ proj) {
    __shared__ float as[32][128];
    __shared__ float bs[32][128];
    int tid = threadIdx.x, tx = tid&15, ty = tid>>4;
    int rbase = blockIdx.y*128, mbase = blockIdx.x*128;
    float acc[8][8] = {};
    for (int kt=0; kt<64; kt+=32) {
        #pragma unroll
        for (int t=0;t<4;t++){
            int q = tid + t*256; int row = q>>3, c = q&7;
            float4 v = *(const float4*)&g_h[(rbase+row)*64 + kt + c*4];
            as[c*4+0][row]=v.x*XSCL; as[c*4+1][row]=v.y*XSCL;
            as[c*4+2][row]=v.z*XSCL; as[c*4+3][row]=v.w*XSCL;
            float4 p = *(const float4*)&proj[(mbase+row)*64 + kt + c*4];
            bs[c*4+0][row]=p.x; bs[c*4+1][row]=p.y; bs[c*4+2][row]=p.z; bs[c*4+3][row]=p.w;
        }
        __syncthreads();
        #pragma unroll
        for (int k=0;k<32;k++){
            float a[8], bv[8];
            #pragma unroll
            for (int i=0;i<8;i++) a[i]=as[k][ty*8+i];
            #pragma unroll
            for (int j=0;j<8;j++) bv[j]=bs[k][tx*8+j];
            #pragma unroll
            for (int i=0;i<8;i++)
                #pragma unroll
                for (int j=0;j<8;j++) acc[i][j]=fmaf(a[i],bv[j],acc[i][j]);
        }
        __syncthreads();
    }
    #pragma unroll
    for (int i=0;i<8;i++)
        #pragma unroll
        for (int j=0;j<8;j++)
            g_u[(rbase+ty*8+i)*256 + mbase+tx*8+j] = acc[i][j];
}

// ---------------- row max (stab_q) ----------------
__global__ void k_stabq() {
    int row = blockIdx.x*8 + (threadIdx.x>>5);
    int l = threadIdx.x & 31;
    const float* u = g_u + (size_t)row*256;
    float m = -1e30f;
    #pragma unroll
    for (int j=0;j<8;j++) m = fmaxf(m, u[l + j*32]);
    #pragma unroll
    for (int o=16;o;o>>=1) m = fmaxf(m, __shfl_xor_sync(~0u,m,o));
    if (l==0) g_stabq[row] = m;
}

// ---------------- per-head max (stab_k) ----------------
__global__ void k_stabk() {
    int g = blockIdx.x, tid = threadIdx.x;
    __shared__ float red[8];
    float m = -1e30f;
    #pragma unroll
    for (int j=0;j<8;j++) m = fmaxf(m, g_stabq[g*2048 + tid + j*256]);
    #pragma unroll
    for (int o=16;o;o>>=1) m = fmaxf(m, __shfl_xor_sync(~0u,m,o));
    if ((tid&31)==0) red[tid>>5] = m;
    __syncthreads();
    if (tid==0){
        float t = red[0];
        #pragma unroll
        for (int i=1;i<8;i++) t = fmaxf(t, red[i]);
        g_stabk[g] = t;
    }
}

// ---------------- e = exp(u - diag - stabq), in place ----------------
__global__ void k_exp() {
    int idx = blockIdx.x*blockDim.x + threadIdx.x;
    int r = idx >> 8;
    g_u[idx] = __expf(g_u[idx] - g_diag[r] - g_stabq[r]);
}

__global__ void k_scale() {
    int r = blockIdx.x*256 + threadIdx.x;
    g_scale[r] = RATIO * __expf(g_stabq[r] - g_stabk[r>>11]);
}

// ---------------- ctx[g] = kp^T @ h : [256 x 2048] @ [2048 x 64] per head ----------------
__global__ void k_ctx() {
    __shared__ float es[32][128];
    __shared__ float hs[32][64];
    int tid = threadIdx.x, tx = tid&15, ty = tid>>4;
    int g = blockIdx.y, mbase = blockIdx.x*128;
    size_t ebase = (size_t)g*2048*256;
    const float* hb = g_h + g*2048*64;
    float acc[8][4] = {};
    for (int n0=0; n0<2048; n0+=32) {
        #pragma unroll
        for (int t=0;t<4;t++){
            int q = tid + t*256; int kk = q>>5, mq = q&31;
            float sc = g_scale[g*2048 + n0 + kk];
            float4 v = *(const float4*)&g_u[ebase + (size_t)(n0+kk)*256 + mbase + mq*4];
            es[kk][mq*4+0]=fmaf(v.x,sc,REPS); es[kk][mq*4+1]=fmaf(v.y,sc,REPS);
            es[kk][mq*4+2]=fmaf(v.z,sc,REPS); es[kk][mq*4+3]=fmaf(v.w,sc,REPS);
        }
        #pragma unroll
        for (int t=0;t<2;t++){
            int q = tid + t*256; int kk = q>>4, dq = q&15;
            *(float4*)&hs[kk][dq*4] = *(const float4*)&hb[(n0+kk)*64 + dq*4];
        }
        __syncthreads();
        #pragma unroll
        for (int k=0;k<32;k++){
            float a[8], bv[4];
            #pragma unroll
            for (int i=0;i<8;i++) a[i]=es[k][ty*8+i];
            #pragma unroll
            for (int j=0;j<4;j++) bv[j]=hs[k][tx*4+j];
            #pragma unroll
            for (int i=0;i<8;i++)
                #pragma unroll
                for (int j=0;j<4;j++) acc[i][j]=fmaf(a[i],bv[j],acc[i][j]);
        }
        __syncthreads();
    }
    #pragma unroll
    for (int i=0;i<8;i++)
        #pragma unroll
        for (int j=0;j<4;j++)
            g_ctx[(g*256 + mbase + ty*8+i)*64 + tx*4+j] = acc[i][j];
}

// ---------------- ksum ----------------
__global__ void k_ksum_init() {
    g_ksum[blockIdx.x*256 + threadIdx.x] = 2048.f * REPS;
}
__global__ void k_ksum() {
    int g = blockIdx.x, nc = blockIdx.y, m = threadIdx.x;
    __shared__ float sc[256];
    sc[m] = g_scale[g*2048 + nc*256 + m];
    __syncthreads();
    const float* e = g_u + ((size_t)(g*2048 + nc*256))*256 + m;
    float acc = 0.f;
    #pragma unroll 4
    for (int n=0; n<256; n++) acc = fmaf(e[(size_t)n*256], sc[n], acc);
    atomicAdd(&g_ksum[g*256 + m], acc);
}

// ---------------- attn = (qp @ ctx) / (qp . ksum); x1 = x + attn ----------------
__global__ void k_attn(const float* __restrict__ x) {
    __shared__ float qs[32][128];
    __shared__ float cs[32][64];
    __shared__ float ks[32];
    __shared__ float sden[128];
    int tid = threadIdx.x, tx = tid&15, ty = tid>>4;
    int g = blockIdx.y, nbase = blockIdx.x*128;
    size_t ebase = (size_t)g*2048*256;
    float acc[8][4] = {}, den[8] = {};
    for (int m0=0; m0<256; m0+=32) {
        #pragma unroll
        for (int t=0;t<4;t++){
            int q = tid + t*256; int nn = q>>3, cq = q&7;
            float4 v = *(const float4*)&g_u[ebase + (size_t)(nbase+nn)*256 + m0 + cq*4];
            qs[cq*4+0][nn]=fmaf(v.x,RATIO,REPS); qs[cq*4+1][nn]=fmaf(v.y,RATIO,REPS);
            qs[cq*4+2][nn]=fmaf(v.z,RATIO,REPS); qs[cq*4+3][nn]=fmaf(v.w,RATIO,REPS);
        }
        #pragma unroll
        for (int t=0;t<2;t++){
            int q = tid + t*256; int kk = q>>4, dq = q&15;
            *(float4*)&cs[kk][dq*4] = *(const float4*)&g_ctx[(g*256 + m0 + kk)*64 + dq*4];
        }
        if (tid < 32) ks[tid] = g_ksum[g*256 + m0 + tid];
        __syncthreads();
        #pragma unroll
        for (int k=0;k<32;k++){
            float a[8], bv[4];
            #pragma unroll
            for (int i=0;i<8;i++) a[i]=qs[k][ty*8+i];
            #pragma unroll
            for (int j=0;j<4;j++) bv[j]=cs[k][tx*4+j];
            #pragma unroll
            for (int i=0;i<8;i++)
                #pragma unroll
                for (int j=0;j<4;j++) acc[i][j]=fmaf(a[i],bv[j],acc[i][j]);
            if (tx==0){
                #pragma unroll
                for (int i=0;i<8;i++) den[i]=fmaf(a[i],ks[k],den[i]);
            }
        }
        __syncthreads();
    }
    if (tx==0){
        #pragma unroll
        for (int i=0;i<8;i++) sden[ty*8+i] = den[i];
    }
    __syncthreads();
    int bb = g/12, hd = g%12;
    #pragma unroll
    for (int i=0;i<8;i++){
        float dinv = 1.f / sden[ty*8+i];
        int n = nbase + ty*8 + i;
        #pragma unroll
        for (int j=0;j<4;j++){
            size_t xi = ((size_t)(bb*2048 + n))*768 + hd*64 + tx*4 + j;
            g_x1[xi] = x[xi] + acc[i][j]*dinv;
        }
    }
}

// ---------------- transpose + tf32 round: in[R x C] -> out[C x R] ----------------
__global__ void k_transpose(const float* __restrict__ in, float* __restrict__ out,
                            int R, int C) {
    __shared__ float t[32][33];
    int bx = blockIdx.x*32, by = blockIdx.y*32;
    int x = threadIdx.x, y = threadIdx.y;   // block(32,8)
    #pragma unroll
    for (int i=0;i<32;i+=8)
        t[y+i][x] = tf32r(in[(size_t)(by+y+i)*C + bx+x]);
    __syncthreads();
    #pragma unroll
    for (int i=0;i<32;i+=8)
        out[(size_t)(bx+y+i)*R + by+x] = t[x][y+i];
}

// ================= tf32 mma.sync GEMM: C[128 x 128] tiles =================
// A: [Mrows x Kdim] row-major (tf32-rounded). Bt: [Ncols x Kdim] row-major
// (tf32-rounded). EPI 0: C=tf32r(gelu(acc+bias)) -> g_mid. EPI 1: C=acc+bias+resid.
#define SMST 36                       // smem row stride (floats), conflict-free frags
#define ASZ  (128*SMST)               // floats per operand stage
#define GSMEM_BYTES (4*ASZ*4)         // A0,B0,A1,B1 = 73728 B

template<int EPI>
__global__ __launch_bounds__(256) void k_gemm_mma(
        const float* __restrict__ A, int lda,
        const float* __restrict__ Bt, int Kdim,
        const float* __restrict__ bias,
        const float* __restrict__ resid,
        float* __restrict__ C, int ldc) {
    extern __shared__ __align__(16) float sm[];
    uint32_t smb = s2u(sm);
    int tid = threadIdx.x, wid = tid>>5, lane = tid&31;
    int wm = (wid&1)*64, wn = (wid>>1)*32;
    int r = lane>>2, cq = lane&3;

    int rbase = blockIdx.y*128, cbase = blockIdx.x*128;
    const float* Ag = A  + (size_t)rbase*lda;
    const float* Bg = Bt + (size_t)cbase*Kdim;
    int KT = Kdim >> 5;

    float acc[4][4][4];
    #pragma unroll
    for (int i=0;i<4;i++)
        #pragma unroll
        for (int j=0;j<4;j++)
            #pragma unroll
            for (int k=0;k<4;k++) acc[i][j][k]=0.f;

    #define LOAD_STAGE(s, kt) do { \
        uint32_t _ab = smb + (uint32_t)((s)*2*ASZ)*4u; \
        uint32_t _bb = _ab + (uint32_t)ASZ*4u; \
        const float* _Ag = Ag + (kt)*32; \
        const float* _Bg = Bg + (kt)*32; \
        _Pragma("unroll") \
        for (int _t=0;_t<4;_t++){ \
            int _q = tid + _t*256; int _r = _q>>3, _c = _q&7; \
            uint32_t _so = (uint32_t)(_r*SMST + _c*4)*4u; \
            cpasync16(_ab+_so, _Ag + (size_t)_r*lda  + _c*4); \
            cpasync16(_bb+_so, _Bg + (size_t)_r*Kdim + _c*4); \
        } \
        asm volatile("cp.async.commit_group;" ::: "memory"); \
    } while(0)

    LOAD_STAGE(0, 0);
    for (int kt=0; kt<KT; kt++){
        int cur = kt & 1;
        if (kt+1 < KT){
            LOAD_STAGE(cur^1, kt+1);
            asm volatile("cp.async.wait_group 1;" ::: "memory");
        } else {
            asm volatile("cp.async.wait_group 0;" ::: "memory");
        }
        __syncthreads();
        const float* As = sm + cur*2*ASZ;
        const float* Bs = As + ASZ;
        #pragma unroll
        for (int ks=0; ks<4; ks++){
            float a[4][4], b[4][2];
            #pragma unroll
            for (int mf=0; mf<4; mf++){
                int base = (wm + mf*16 + r)*SMST + ks*8 + cq;
                a[mf][0] = As[base];
                a[mf][1] = As[base + 8*SMST];
                a[mf][2] = As[base + 4];
                a[mf][3] = As[base + 8*SMST + 4];
            }
            #pragma unroll
            for (int nf=0; nf<4; nf++){
                int nb = (wn + nf*8 + r)*SMST + ks*8 + cq;
                b[nf][0] = Bs[nb];
                b[nf][1] = Bs[nb + 4];
            }
            #pragma unroll
            for (int mf=0; mf<4; mf++)
                #pragma unroll
                for (int nf=0; nf<4; nf++)
                    mma8(acc[mf][nf], a[mf], b[nf]);
        }
        __syncthreads();
    }
    #undef LOAD_STAGE

    // Epilogue: stage tile in smem (stride 132) for coalesced stores
    float* stg = sm;
    #pragma unroll
    for (int mf=0; mf<4; mf++)
        #pragma unroll
        for (int nf=0; nf<4; nf++){
            int row = wm + mf*16 + r, col = wn + nf*8 + 2*cq;
            *(float2*)&stg[row*132 + col]       = make_float2(acc[mf][nf][0], acc[mf][nf][1]);
            *(float2*)&stg[(row+8)*132 + col]   = make_float2(acc[mf][nf][2], acc[mf][nf][3]);
        }
    __syncthreads();
    #pragma unroll
    for (int t=0;t<16;t++){
        int q = tid + t*256; int row = q>>5, c4 = (q&31)*4;
        float4 v = *(const float4*)&stg[row*132 + c4];
        int col = cbase + c4;
        size_t oi = (size_t)(rbase + row)*ldc + col;
        if (EPI == 0){
            v.x += bias[col+0]; v.y += bias[col+1]; v.z += bias[col+2]; v.w += bias[col+3];
            v.x = tf32r(0.5f*v.x*(1.f+erff(v.x*0.70710678118654752f)));
            v.y = tf32r(0.5f*v.y*(1.f+erff(v.y*0.70710678118654752f)));
            v.z = tf32r(0.5f*v.z*(1.f+erff(v.z*0.70710678118654752f)));
            v.w = tf32r(0.5f*v.w*(1.f+erff(v.w*0.70710678118654752f)));
            *(float4*)&C[oi] = v;
        } else {
            float4 rv = *(const float4*)&resid[oi];
            v.x += bias[col+0] + rv.x; v.y += bias[col+1] + rv.y;
            v.z += bias[col+2] + rv.z; v.w += bias[col+3] + rv.w;
            *(float4*)&C[oi] = v;
        }
    }
}

extern "C" void kernel_launch(void* const* d_in, const int* in_sizes, int n_in,
                              void* d_out, int out_size) {
    const float* x    = (const float*)d_in[0];
    const float* proj = (const float*)d_in[1];
    const float* ln1g = (const float*)d_in[2];
    const float* ln1b = (const float*)d_in[3];
    const float* ln2g = (const float*)d_in[4];
    const float* ln2b = (const float*)d_in[5];
    const float* W1   = (const float*)d_in[6];
    const float* b1   = (const float*)d_in[7];
    const float* W2   = (const float*)d_in[8];
    const float* b2   = (const float*)d_in[9];
    float* out = (float*)d_out;

    cudaFuncSetAttribute(k_gemm_mma<0>, cudaFuncAttributeMaxDynamicSharedMemorySize, GSMEM_BYTES);
    cudaFuncSetAttribute(k_gemm_mma<1>, cudaFuncAttributeMaxDynamicSharedMemorySize, GSMEM_BYTES);

    float* w1t; cudaGetSymbolAddress((void**)&w1t, g_w1t);
    float* w2t; cudaGetSymbolAddress((void**)&w2t, g_w2t);
    float* h2;  cudaGetSymbolAddress((void**)&h2,  g_h2);
    float* mid; cudaGetSymbolAddress((void**)&mid, g_mid);
    float* x1;  cudaGetSymbolAddress((void**)&x1,  g_x1);

    k_ln1<<<BN, Eq>>>(x, ln1g, ln1b);
    k_ugemm<<<dim3(2, ROWS/128), 256>>>(proj);
    k_stabq<<<ROWS/8, 256>>>();
    k_stabk<<<Bq*Hq, 256>>>();
    k_exp<<<(ROWS*Mq)/512, 512>>>();
    k_scale<<<ROWS/256, 256>>>();
    k_ksum_init<<<Bq*Hq, 256>>>();
    k_ctx<<<dim3(2, Bq*Hq), 256>>>();
    k_ksum<<<dim3(Bq*Hq, 8), 256>>>();
    k_attn<<<dim3(Nq/128, Bq*Hq), 256>>>(x);
    k_ln2<<<BN, Eq>>>(ln2g, ln2b);

    // weight transposes (tf32-rounded)
    k_transpose<<<dim3(Fq/32, Eq/32), dim3(32,8)>>>(W1, w1t, Eq, Fq);   // W1[768x3072] -> [3072x768]
    k_transpose<<<dim3(Eq/32, Fq/32), dim3(32,8)>>>(W2, w2t, Fq, Eq);   // W2[3072x768] -> [768x3072]

    // MLP GEMM1: [8192x768]@[768x3072] -> g_mid (gelu)
    k_gemm_mma<0><<<dim3(Fq/128, BN/128), 256, GSMEM_BYTES>>>(h2, Eq, w1t, Eq, b1, nullptr, mid, Fq);
    // MLP GEMM2: [8192x3072]@[3072x768] + bias + x1 -> out
    k_gemm_mma<1><<<dim3(Eq/128, BN/128), 256, GSMEM_BYTES>>>(mid, Fq, w2t, Fq, b2, x1, out, Eq);
}

// round 4
// speedup vs baseline: 2.2871x; 1.0944x over previous
#include <cuda_runtime.h>
#include <math.h>
#include <stdint.h>

// Shapes (fixed by the problem)
#define Bq 4
#define Nq 2048
#define Eq 768
#define Hq 12
#define Mq 256
#define Dhq 64
#define Fq 3072
#define ROWS (Bq*Hq*Nq)   // 98304
#define BN (Bq*Nq)        // 8192

#define RATIO 0.0625f            // M^-0.5
#define REPS  6.25e-6f           // RATIO * EPS(1e-4)
#define XSCL  0.35355339059327373f  // Dh^-0.25

// Scratch (device globals; allocation-free)
__device__ float g_h[ROWS*Dhq];      // LN1 out (unscaled values), head layout
__device__ float g_hs[ROWS*Dhq];     // tf32r(y*XSCL) for u-GEMM A operand
__device__ float g_projr[Mq*Dhq];    // tf32-rounded proj
__device__ float g_u[ROWS*Mq];       // u, then e = exp(u - diag - stabq)
__device__ float g_diag[ROWS];
__device__ float g_stabq[ROWS];
__device__ float g_scale[ROWS];      // 0.0625*exp(stabq - stabk)
__device__ float g_stabk[Bq*Hq];
__device__ float g_ctx[Bq*Hq*Mq*Dhq];
__device__ float g_ksum[Bq*Hq*Mq];
__device__ float g_x1[BN*Eq];        // x + attn
__device__ float g_h2[BN*Eq];        // LN2 out (tf32-rounded)
__device__ float g_mid[BN*Fq];       // gelu(h2@W1+b1) (tf32-rounded)
__device__ float g_w1t[Fq*Eq];       // W1^T [3072 x 768], tf32-rounded
__device__ float g_w2t[Eq*Fq];       // W2^T [768 x 3072], tf32-rounded

// ======================= helpers =======================
__device__ __forceinline__ uint32_t s2u(const void* p){
    uint32_t a;
    asm("{ .reg .u64 t; cvta.to.shared.u64 t, %1; cvt.u32.u64 %0, t; }":"=r"(a):"l"(p));
    return a;
}
__device__ __forceinline__ float tf32r(float x){
    float y; asm("cvt.rna.tf32.f32 %0, %1;":"=f"(y):"f"(x)); return y;
}
__device__ __forceinline__ void cpasync16(uint32_t sa, const void* ga){
    asm volatile("cp.async.cg.shared.global [%0], [%1], 16;" :: "r"(sa), "l"(ga));
}
// warp-level tf32 MMA (sm_80 baseline; valid on plain sm_103 target)
__device__ __forceinline__ void mma8(float* d, const float* a, const float* b){
    asm volatile("mma.sync.aligned.m16n8k8.row.col.f32.tf32.tf32.f32 "
        "{%0,%1,%2,%3}, {%4,%5,%6,%7}, {%8,%9}, {%0,%1,%2,%3};"
        : "+f"(d[0]),"+f"(d[1]),"+f"(d[2]),"+f"(d[3])
        : "r"(__float_as_uint(a[0])),"r"(__float_as_uint(a[1])),
          "r"(__float_as_uint(a[2])),"r"(__float_as_uint(a[3])),
          "r"(__float_as_uint(b[0])),"r"(__float_as_uint(b[1])));
}

// ---------------- LN1: per-token layernorm + head-layout write + diag ----------------
__global__ void k_ln1(const float* __restrict__ x, const float* __restrict__ g,
                      const float* __restrict__ b) {
    int row = blockIdx.x;           // 0..8191
    int tid = threadIdx.x;          // 768 threads
    float v = x[row*Eq + tid];
    __shared__ float red[48];
    __shared__ float mv[2];
    float s1 = v, s2 = v*v;
    #pragma unroll
    for (int o=16;o;o>>=1){ s1+=__shfl_xor_sync(~0u,s1,o); s2+=__shfl_xor_sync(~0u,s2,o); }
    int w = tid>>5, l = tid&31;
    if (l==0){ red[w]=s1; red[24+w]=s2; }
    __syncthreads();
    if (tid<32){
        float a = tid<24 ? red[tid]    : 0.f;
        float c = tid<24 ? red[24+tid] : 0.f;
        #pragma unroll
        for (int o=16;o;o>>=1){ a+=__shfl_xor_sync(~0u,a,o); c+=__shfl_xor_sync(~0u,c,o); }
        if (tid==0){ float m=a*(1.f/Eq); mv[0]=m; mv[1]=rsqrtf(c*(1.f/Eq)-m*m+1e-5f); }
    }
    __syncthreads();
    float y = (v - mv[0]) * mv[1] * g[tid] + b[tid];
    int bb = row>>11, n = row&2047, hd = tid>>6, d = tid&63;
    size_t hidx = ((size_t)(bb*Hq+hd)*Nq + n)*Dhq + d;
    g_h[hidx]  = y;
    g_hs[hidx] = tf32r(y * XSCL);
    __shared__ float sdg[Hq];
    if (tid < Hq) sdg[tid] = 0.f;
    __syncthreads();
    float yy = y*y;
    #pragma unroll
    for (int o=16;o;o>>=1) yy += __shfl_xor_sync(~0u,yy,o);
    if (l==0) atomicAdd(&sdg[w>>1], yy);
    __syncthreads();
    if (tid < Hq) g_diag[(bb*Hq+tid)*Nq + n] = 0.0625f * sdg[tid];
}

// ---------------- LN2: plain row-major out (tf32-rounded for MMA) ----------------
__global__ void k_ln2(const float* __restrict__ g, const float* __restrict__ b) {
    int row = blockIdx.x;
    int tid = threadIdx.x;
    float v = g_x1[row*Eq + tid];
    __shared__ float red[48];
    __shared__ float mv[2];
    float s1 = v, s2 = v*v;
    #pragma unroll
    for (int o=16;o;o>>=1){ s1+=__shfl_xor_sync(~0u,s1,o); s2+=__shfl_xor_sync(~0u,s2,o); }
    int w = tid>>5, l = tid&31;
    if (l==0){ red[w]=s1; red[24+w]=s2; }
    __syncthreads();
    if (tid<32){
        float a = tid<24 ? red[tid]    : 0.f;
        float c = tid<24 ? red[24+tid] : 0.f;
        #pragma unroll
        for (int o=16;o;o>>=1){ a+=__shfl_xor_sync(~0u,a,o); c+=__shfl_xor_sync(~0u,c,o); }
        if (tid==0){ float m=a*(1.f/Eq); mv[0]=m; mv[1]=rsqrtf(c*(1.f/Eq)-m*m+1e-5f); }
    }
    __syncthreads();
    g_h2[row*Eq + tid] = tf32r((v - mv[0]) * mv[1] * g[tid] + b[tid]);
}

// ---------------- tf32-round proj ----------------
__global__ void k_roundproj(const float* __restrict__ proj) {
    int i = blockIdx.x*256 + threadIdx.x;
    g_projr[i] = tf32r(proj[i]);
}

// ---------------- row max (stab_q) ----------------
__global__ void k_stabq() {
    int row = blockIdx.x*8 + (threadIdx.x>>5);
    int l = threadIdx.x & 31;
    const float* u = g_u + (size_t)row*256;
    float m = -1e30f;
    #pragma unroll
    for (int j=0;j<8;j++) m = fmaxf(m, u[l + j*32]);
    #pragma unroll
    for (int o=16;o;o>>=1) m = fmaxf(m, __shfl_xor_sync(~0u,m,o));
    if (l==0) g_stabq[row] = m;
}

// ---------------- per-head max (stab_k) ----------------
__global__ void k_stabk() {
    int g = blockIdx.x, tid = threadIdx.x;
    __shared__ float red[8];
    float m = -1e30f;
    #pragma unroll
    for (int j=0;j<8;j++) m = fmaxf(m, g_stabq[g*2048 + tid + j*256]);
    #pragma unroll
    for (int o=16;o;o>>=1) m = fmaxf(m, __shfl_xor_sync(~0u,m,o));
    if ((tid&31)==0) red[tid>>5] = m;
    __syncthreads();
    if (tid==0){
        float t = red[0];
        #pragma unroll
        for (int i=1;i<8;i++) t = fmaxf(t, red[i]);
        g_stabk[g] = t;
    }
}

// ---------------- e = exp(u - diag - stabq), in place ----------------
__global__ void k_exp() {
    int idx = blockIdx.x*blockDim.x + threadIdx.x;
    int r = idx >> 8;
    g_u[idx] = __expf(g_u[idx] - g_diag[r] - g_stabq[r]);
}

__global__ void k_scale() {
    int r = blockIdx.x*256 + threadIdx.x;
    g_scale[r] = RATIO * __expf(g_stabq[r] - g_stabk[r>>11]);
}

// ---------------- ctx[g] = kp^T @ h : [256 x 2048] @ [2048 x 64] per head ----------------
__global__ void k_ctx() {
    __shared__ float es[32][128];
    __shared__ float hs[32][64];
    int tid = threadIdx.x, tx = tid&15, ty = tid>>4;
    int g = blockIdx.y, mbase = blockIdx.x*128;
    size_t ebase = (size_t)g*2048*256;
    const float* hb = g_h + (size_t)g*2048*64;
    float acc[8][4] = {};
    for (int n0=0; n0<2048; n0+=32) {
        #pragma unroll
        for (int t=0;t<4;t++){
            int q = tid + t*256; int kk = q>>5, mq = q&31;
            float sc = g_scale[g*2048 + n0 + kk];
            float4 v = *(const float4*)&g_u[ebase + (size_t)(n0+kk)*256 + mbase + mq*4];
            es[kk][mq*4+0]=fmaf(v.x,sc,REPS); es[kk][mq*4+1]=fmaf(v.y,sc,REPS);
            es[kk][mq*4+2]=fmaf(v.z,sc,REPS); es[kk][mq*4+3]=fmaf(v.w,sc,REPS);
        }
        #pragma unroll
        for (int t=0;t<2;t++){
            int q = tid + t*256; int kk = q>>4, dq = q&15;
            *(float4*)&hs[kk][dq*4] = *(const float4*)&hb[(n0+kk)*64 + dq*4];
        }
        __syncthreads();
        #pragma unroll
        for (int k=0;k<32;k++){
            float a[8], bv[4];
            #pragma unroll
            for (int i=0;i<8;i++) a[i]=es[k][ty*8+i];
            #pragma unroll
            for (int j=0;j<4;j++) bv[j]=hs[k][tx*4+j];
            #pragma unroll
            for (int i=0;i<8;i++)
                #pragma unroll
                for (int j=0;j<4;j++) acc[i][j]=fmaf(a[i],bv[j],acc[i][j]);
        }
        __syncthreads();
    }
    #pragma unroll
    for (int i=0;i<8;i++)
        #pragma unroll
        for (int j=0;j<4;j++)
            g_ctx[(g*256 + mbase + ty*8+i)*64 + tx*4+j] = acc[i][j];
}

// ---------------- ksum ----------------
__global__ void k_ksum_init() {
    g_ksum[blockIdx.x*256 + threadIdx.x] = 2048.f * REPS;
}
__global__ void k_ksum() {
    int g = blockIdx.x, nc = blockIdx.y, m = threadIdx.x;
    __shared__ float sc[256];
    sc[m] = g_scale[g*2048 + nc*256 + m];
    __syncthreads();
    const float* e = g_u + ((size_t)(g*2048 + nc*256))*256 + m;
    float acc = 0.f;
    #pragma unroll 4
    for (int n=0; n<256; n++) acc = fmaf(e[(size_t)n*256], sc[n], acc);
    atomicAdd(&g_ksum[g*256 + m], acc);
}

// ---------------- attn = (qp @ ctx) / (qp . ksum); x1 = x + attn ----------------
__global__ void k_attn(const float* __restrict__ x) {
    __shared__ float qs[32][128];
    __shared__ float cs[32][64];
    __shared__ float ks[32];
    __shared__ float sden[128];
    int tid = threadIdx.x, tx = tid&15, ty = tid>>4;
    int g = blockIdx.y, nbase = blockIdx.x*128;
    size_t ebase = (size_t)g*2048*256;
    float acc[8][4] = {}, den[8] = {};
    for (int m0=0; m0<256; m0+=32) {
        #pragma unroll
        for (int t=0;t<4;t++){
            int q = tid + t*256; int nn = q>>3, cq = q&7;
            float4 v = *(const float4*)&g_u[ebase + (size_t)(nbase+nn)*256 + m0 + cq*4];
            qs[cq*4+0][nn]=fmaf(v.x,RATIO,REPS); qs[cq*4+1][nn]=fmaf(v.y,RATIO,REPS);
            qs[cq*4+2][nn]=fmaf(v.z,RATIO,REPS); qs[cq*4+3][nn]=fmaf(v.w,RATIO,REPS);
        }
        #pragma unroll
        for (int t=0;t<2;t++){
            int q = tid + t*256; int kk = q>>4, dq = q&15;
            *(float4*)&cs[kk][dq*4] = *(const float4*)&g_ctx[(g*256 + m0 + kk)*64 + dq*4];
        }
        if (tid < 32) ks[tid] = g_ksum[g*256 + m0 + tid];
        __syncthreads();
        #pragma unroll
        for (int k=0;k<32;k++){
            float a[8], bv[4];
            #pragma unroll
            for (int i=0;i<8;i++) a[i]=qs[k][ty*8+i];
            #pragma unroll
            for (int j=0;j<4;j++) bv[j]=cs[k][tx*4+j];
            #pragma unroll
            for (int i=0;i<8;i++)
                #pragma unroll
                for (int j=0;j<4;j++) acc[i][j]=fmaf(a[i],bv[j],acc[i][j]);
            if (tx==0){
                #pragma unroll
                for (int i=0;i<8;i++) den[i]=fmaf(a[i],ks[k],den[i]);
            }
        }
        __syncthreads();
    }
    if (tx==0){
        #pragma unroll
        for (int i=0;i<8;i++) sden[ty*8+i] = den[i];
    }
    __syncthreads();
    int bb = g/12, hd = g%12;
    #pragma unroll
    for (int i=0;i<8;i++){
        float dinv = 1.f / sden[ty*8+i];
        int n = nbase + ty*8 + i;
        #pragma unroll
        for (int j=0;j<4;j++){
            size_t xi = ((size_t)(bb*2048 + n))*768 + hd*64 + tx*4 + j;
            g_x1[xi] = x[xi] + acc[i][j]*dinv;
        }
    }
}

// ---------------- transpose + tf32 round: in[R x C] -> out[C x R] ----------------
__global__ void k_transpose(const float* __restrict__ in, float* __restrict__ out,
                            int R, int C) {
    __shared__ float t[32][33];
    int bx = blockIdx.x*32, by = blockIdx.y*32;
    int x = threadIdx.x, y = threadIdx.y;   // block(32,8)
    #pragma unroll
    for (int i=0;i<32;i+=8)
        t[y+i][x] = tf32r(in[(size_t)(by+y+i)*C + bx+x]);
    __syncthreads();
    #pragma unroll
    for (int i=0;i<32;i+=8)
        out[(size_t)(bx+y+i)*R + by+x] = t[x][y+i];
}

// ================= tf32 mma.sync GEMM: C[128 x 128] tiles =================
// A: [Mrows x Kdim] row-major (tf32-rounded). Bt: [Ncols x Kdim] row-major
// (tf32-rounded). EPI 0: C=tf32r(gelu(acc+bias)). EPI 1: C=acc+bias+resid.
// EPI 2: C=acc (plain store).
#define SMST 36                       // smem row stride (floats), conflict-free frags
#define ASZ  (128*SMST)               // floats per operand stage
#define GSMEM_BYTES (4*ASZ*4)         // A0,B0,A1,B1 = 73728 B

template<int EPI>
__global__ __launch_bounds__(256, 2) void k_gemm_mma(
        const float* __restrict__ A, int lda,
        const float* __restrict__ Bt, int Kdim,
        const float* __restrict__ bias,
        const float* __restrict__ resid,
        float* __restrict__ C, int ldc) {
    extern __shared__ __align__(16) float sm[];
    uint32_t smb = s2u(sm);
    int tid = threadIdx.x, wid = tid>>5, lane = tid&31;
    int wm = (wid&1)*64, wn = (wid>>1)*32;
    int r = lane>>2, cq = lane&3;

    int rbase = blockIdx.y*128, cbase = blockIdx.x*128;
    const float* Ag = A  + (size_t)rbase*lda;
    const float* Bg = Bt + (size_t)cbase*Kdim;
    int KT = Kdim >> 5;

    float acc[4][4][4];
    #pragma unroll
    for (int i=0;i<4;i++)
        #pragma unroll
        for (int j=0;j<4;j++)
            #pragma unroll
            for (int k=0;k<4;k++) acc[i][j][k]=0.f;

    #define LOAD_STAGE(s, kt) do { \
        uint32_t _ab = smb + (uint32_t)((s)*2*ASZ)*4u; \
        uint32_t _bb = _ab + (uint32_t)ASZ*4u; \
        const float* _Ag = Ag + (kt)*32; \
        const float* _Bg = Bg + (kt)*32; \
        _Pragma("unroll") \
        for (int _t=0;_t<4;_t++){ \
            int _q = tid + _t*256; int _r = _q>>3, _c = _q&7; \
            uint32_t _so = (uint32_t)(_r*SMST + _c*4)*4u; \
            cpasync16(_ab+_so, _Ag + (size_t)_r*lda  + _c*4); \
            cpasync16(_bb+_so, _Bg + (size_t)_r*Kdim + _c*4); \
        } \
        asm volatile("cp.async.commit_group;" ::: "memory"); \
    } while(0)

    LOAD_STAGE(0, 0);
    for (int kt=0; kt<KT; kt++){
        int cur = kt & 1;
        if (kt+1 < KT){
            LOAD_STAGE(cur^1, kt+1);
            asm volatile("cp.async.wait_group 1;" ::: "memory");
        } else {
            asm volatile("cp.async.wait_group 0;" ::: "memory");
        }
        __syncthreads();
        const float* As = sm + cur*2*ASZ;
        const float* Bs = As + ASZ;
        #pragma unroll
        for (int ks=0; ks<4; ks++){
            float a[4][4], b[4][2];
            #pragma unroll
            for (int mf=0; mf<4; mf++){
                int base = (wm + mf*16 + r)*SMST + ks*8 + cq;
                a[mf][0] = As[base];
                a[mf][1] = As[base + 8*SMST];
                a[mf][2] = As[base + 4];
                a[mf][3] = As[base + 8*SMST + 4];
            }
            #pragma unroll
            for (int nf=0; nf<4; nf++){
                int nb = (wn + nf*8 + r)*SMST + ks*8 + cq;
                b[nf][0] = Bs[nb];
                b[nf][1] = Bs[nb + 4];
            }
            #pragma unroll
            for (int mf=0; mf<4; mf++)
                #pragma unroll
                for (int nf=0; nf<4; nf++)
                    mma8(acc[mf][nf], a[mf], b[nf]);
        }
        __syncthreads();
    }
    #undef LOAD_STAGE

    // Epilogue: stage tile in smem (stride 132) for coalesced stores
    float* stg = sm;
    #pragma unroll
    for (int mf=0; mf<4; mf++)
        #pragma unroll
        for (int nf=0; nf<4; nf++){
            int row = wm + mf*16 + r, col = wn + nf*8 + 2*cq;
            *(float2*)&stg[row*132 + col]       = make_float2(acc[mf][nf][0], acc[mf][nf][1]);
            *(float2*)&stg[(row+8)*132 + col]   = make_float2(acc[mf][nf][2], acc[mf][nf][3]);
        }
    __syncthreads();
    #pragma unroll
    for (int t=0;t<16;t++){
        int q = tid + t*256; int row = q>>5, c4 = (q&31)*4;
        float4 v = *(const float4*)&stg[row*132 + c4];
        int col = cbase + c4;
        size_t oi = (size_t)(rbase + row)*ldc + col;
        if (EPI == 0){
            v.x += bias[col+0]; v.y += bias[col+1]; v.z += bias[col+2]; v.w += bias[col+3];
            v.x = tf32r(0.5f*v.x*(1.f+erff(v.x*0.70710678118654752f)));
            v.y = tf32r(0.5f*v.y*(1.f+erff(v.y*0.70710678118654752f)));
            v.z = tf32r(0.5f*v.z*(1.f+erff(v.z*0.70710678118654752f)));
            v.w = tf32r(0.5f*v.w*(1.f+erff(v.w*0.70710678118654752f)));
            *(float4*)&C[oi] = v;
        } else if (EPI == 1){
            float4 rv = *(const float4*)&resid[oi];
            v.x += bias[col+0] + rv.x; v.y += bias[col+1] + rv.y;
            v.z += bias[col+2] + rv.z; v.w += bias[col+3] + rv.w;
            *(float4*)&C[oi] = v;
        } else {
            *(float4*)&C[oi] = v;
        }
    }
}

extern "C" void kernel_launch(void* const* d_in, const int* in_sizes, int n_in,
                              void* d_out, int out_size) {
    const float* x    = (const float*)d_in[0];
    const float* proj = (const float*)d_in[1];
    const float* ln1g = (const float*)d_in[2];
    const float* ln1b = (const float*)d_in[3];
    const float* ln2g = (const float*)d_in[4];
    const float* ln2b = (const float*)d_in[5];
    const float* W1   = (const float*)d_in[6];
    const float* b1   = (const float*)d_in[7];
    const float* W2   = (const float*)d_in[8];
    const float* b2   = (const float*)d_in[9];
    float* out = (float*)d_out;

    cudaFuncSetAttribute(k_gemm_mma<0>, cudaFuncAttributeMaxDynamicSharedMemorySize, GSMEM_BYTES);
    cudaFuncSetAttribute(k_gemm_mma<1>, cudaFuncAttributeMaxDynamicSharedMemorySize, GSMEM_BYTES);
    cudaFuncSetAttribute(k_gemm_mma<2>, cudaFuncAttributeMaxDynamicSharedMemorySize, GSMEM_BYTES);

    float* w1t;  cudaGetSymbolAddress((void**)&w1t,  g_w1t);
    float* w2t;  cudaGetSymbolAddress((void**)&w2t,  g_w2t);
    float* h2;   cudaGetSymbolAddress((void**)&h2,   g_h2);
    float* mid;  cudaGetSymbolAddress((void**)&mid,  g_mid);
    float* x1;   cudaGetSymbolAddress((void**)&x1,   g_x1);
    float* hs;   cudaGetSymbolAddress((void**)&hs,   g_hs);
    float* prj;  cudaGetSymbolAddress((void**)&prj,  g_projr);
    float* u;    cudaGetSymbolAddress((void**)&u,    g_u);

    k_ln1<<<BN, Eq>>>(x, ln1g, ln1b);
    k_roundproj<<<Mq*Dhq/256, 256>>>(proj);
    // u = g_hs @ projr^T : [98304 x 64] @ [64 x 256] on tensor pipe
    k_gemm_mma<2><<<dim3(Mq/128, ROWS/128), 256, GSMEM_BYTES>>>(hs, Dhq, prj, Dhq, nullptr, nullptr, u, Mq);
    k_stabq<<<ROWS/8, 256>>>();
    k_stabk<<<Bq*Hq, 256>>>();
    k_exp<<<(ROWS*Mq)/512, 512>>>();
    k_scale<<<ROWS/256, 256>>>();
    k_ksum_init<<<Bq*Hq, 256>>>();
    k_ctx<<<dim3(2, Bq*Hq), 256>>>();
    k_ksum<<<dim3(Bq*Hq, 8), 256>>>();
    k_attn<<<dim3(Nq/128, Bq*Hq), 256>>>(x);
    k_ln2<<<BN, Eq>>>(ln2g, ln2b);

    // weight transposes (tf32-rounded)
    k_transpose<<<dim3(Fq/32, Eq/32), dim3(32,8)>>>(W1, w1t, Eq, Fq);   // W1[768x3072] -> [3072x768]
    k_transpose<<<dim3(Eq/32, Fq/32), dim3(32,8)>>>(W2, w2t, Fq, Eq);   // W2[3072x768] -> [768x3072]

    // MLP GEMM1: [8192x768]@[768x3072] -> g_mid (gelu)
    k_gemm_mma<0><<<dim3(Fq/128, BN/128), 256, GSMEM_BYTES>>>(h2, Eq, w1t, Eq, b1, nullptr, mid, Fq);
    // MLP GEMM2: [8192x3072]@[3072x768] + bias + x1 -> out
    k_gemm_mma<1><<<dim3(Eq/128, BN/128), 256, GSMEM_BYTES>>>(mid, Fq, w2t, Fq, b2, x1, out, Eq);
}

// round 6
// speedup vs baseline: 3.3635x; 1.4707x over previous
#include <cuda_runtime.h>
#include <cuda_fp16.h>
#include <math.h>
#include <stdint.h>

// Shapes (fixed by the problem)
#define Bq 4
#define Nq 2048
#define Eq 768
#define Hq 12
#define Mq 256
#define Dhq 64
#define Fq 3072
#define ROWS (Bq*Hq*Nq)   // 98304
#define BN (Bq*Nq)        // 8192

#define RATIO 0.0625f            // M^-0.5
#define REPS  6.25e-6f           // RATIO * EPS(1e-4)
#define XSCL  0.35355339059327373f  // Dh^-0.25

// Scratch (device globals; allocation-free)
__device__ float  g_h[ROWS*Dhq];      // LN1 out (unscaled), head layout
__device__ __half g_hsh[ROWS*Dhq];    // half(y*XSCL) for u-GEMM A
__device__ __half g_projh[Mq*Dhq];    // half proj
__device__ float  g_u[ROWS*Mq];       // u, then e = exp(u - diag - stabq)
__device__ float  g_diag[ROWS];
__device__ float  g_stabq[ROWS];
__device__ float  g_scale[ROWS];      // 0.0625*exp(stabq - stabk)
__device__ float  g_stabk[Bq*Hq];
__device__ float  g_ctx[Bq*Hq*Mq*Dhq];
__device__ float  g_ksum[Bq*Hq*Mq];
__device__ float  g_x1[BN*Eq];        // x + attn
__device__ __half g_h2h[BN*Eq];       // LN2 out (half)
__device__ __half g_midh[BN*Fq];      // gelu(h2@W1+b1) (half)
__device__ __half g_w1h[Fq*Eq];       // W1^T half
__device__ __half g_w2h[Eq*Fq];       // W2^T half

// ======================= helpers =======================
__device__ __forceinline__ uint32_t s2u(const void* p){
    uint32_t a;
    asm("{ .reg .u64 t; cvta.to.shared.u64 t, %1; cvt.u32.u64 %0, t; }":"=r"(a):"l"(p));
    return a;
}
__device__ __forceinline__ void cpasync16(uint32_t sa, const void* ga){
    asm volatile("cp.async.cg.shared.global [%0], [%1], 16;" :: "r"(sa), "l"(ga));
}
// f16 MMA, f32 accum (sm_80 baseline; valid on plain sm_103 target)
__device__ __forceinline__ void mma16(float* d, const uint32_t* a, const uint32_t* b){
    asm volatile("mma.sync.aligned.m16n8k16.row.col.f32.f16.f16.f32 "
        "{%0,%1,%2,%3}, {%4,%5,%6,%7}, {%8,%9}, {%0,%1,%2,%3};"
        : "+f"(d[0]),"+f"(d[1]),"+f"(d[2]),"+f"(d[3])
        : "r"(a[0]),"r"(a[1]),"r"(a[2]),"r"(a[3]),"r"(b[0]),"r"(b[1]));
}

// ---------------- LN1: per-token layernorm + head-layout write + diag ----------------
__global__ void k_ln1(const float* __restrict__ x, const float* __restrict__ g,
                      const float* __restrict__ b) {
    int row = blockIdx.x;           // 0..8191
    int tid = threadIdx.x;          // 768 threads
    float v = x[row*Eq + tid];
    __shared__ float red[48];
    __shared__ float mv[2];
    float s1 = v, s2 = v*v;
    #pragma unroll
    for (int o=16;o;o>>=1){ s1+=__shfl_xor_sync(~0u,s1,o); s2+=__shfl_xor_sync(~0u,s2,o); }
    int w = tid>>5, l = tid&31;
    if (l==0){ red[w]=s1; red[24+w]=s2; }
    __syncthreads();
    if (tid<32){
        float a = tid<24 ? red[tid]    : 0.f;
        float c = tid<24 ? red[24+tid] : 0.f;
        #pragma unroll
        for (int o=16;o;o>>=1){ a+=__shfl_xor_sync(~0u,a,o); c+=__shfl_xor_sync(~0u,c,o); }
        if (tid==0){ float m=a*(1.f/Eq); mv[0]=m; mv[1]=rsqrtf(c*(1.f/Eq)-m*m+1e-5f); }
    }
    __syncthreads();
    float y = (v - mv[0]) * mv[1] * g[tid] + b[tid];
    int bb = row>>11, n = row&2047, hd = tid>>6, d = tid&63;
    size_t hidx = ((size_t)(bb*Hq+hd)*Nq + n)*Dhq + d;
    g_h[hidx]   = y;
    g_hsh[hidx] = __float2half(y * XSCL);
    __shared__ float sdg[Hq];
    if (tid < Hq) sdg[tid] = 0.f;
    __syncthreads();
    float yy = y*y;
    #pragma unroll
    for (int o=16;o;o>>=1) yy += __shfl_xor_sync(~0u,yy,o);
    if (l==0) atomicAdd(&sdg[w>>1], yy);
    __syncthreads();
    if (tid < Hq) g_diag[(bb*Hq+tid)*Nq + n] = 0.0625f * sdg[tid];
}

// ---------------- LN2: plain row-major half out ----------------
__global__ void k_ln2(const float* __restrict__ g, const float* __restrict__ b) {
    int row = blockIdx.x;
    int tid = threadIdx.x;
    float v = g_x1[row*Eq + tid];
    __shared__ float red[48];
    __shared__ float mv[2];
    float s1 = v, s2 = v*v;
    #pragma unroll
    for (int o=16;o;o>>=1){ s1+=__shfl_xor_sync(~0u,s1,o); s2+=__shfl_xor_sync(~0u,s2,o); }
    int w = tid>>5, l = tid&31;
    if (l==0){ red[w]=s1; red[24+w]=s2; }
    __syncthreads();
    if (tid<32){
        float a = tid<24 ? red[tid]    : 0.f;
        float c = tid<24 ? red[24+tid] : 0.f;
        #pragma unroll
        for (int o=16;o;o>>=1){ a+=__shfl_xor_sync(~0u,a,o); c+=__shfl_xor_sync(~0u,c,o); }
        if (tid==0){ float m=a*(1.f/Eq); mv[0]=m; mv[1]=rsqrtf(c*(1.f/Eq)-m*m+1e-5f); }
    }
    __syncthreads();
    g_h2h[row*Eq + tid] = __float2half((v - mv[0]) * mv[1] * g[tid] + b[tid]);
}

// ---------------- half-round proj ----------------
__global__ void k_roundproj(const float* __restrict__ proj) {
    int i = blockIdx.x*256 + threadIdx.x;
    g_projh[i] = __float2half(proj[i]);
}

// ---------------- fused: row max (stab_q) + e = exp(u - diag - stabq) ----------------
__global__ void k_stabq_exp() {
    int row = blockIdx.x*8 + (threadIdx.x>>5);
    int l = threadIdx.x & 31;
    float* u = g_u + (size_t)row*256;
    float v[8];
    float m = -1e30f;
    #pragma unroll
    for (int j=0;j<8;j++){ v[j] = u[l + j*32]; m = fmaxf(m, v[j]); }
    #pragma unroll
    for (int o=16;o;o>>=1) m = fmaxf(m, __shfl_xor_sync(~0u,m,o));
    if (l==0) g_stabq[row] = m;
    float d = g_diag[row] + m;
    #pragma unroll
    for (int j=0;j<8;j++) u[l + j*32] = __expf(v[j] - d);
}

// ---------------- per-head max (stab_k) ----------------
__global__ void k_stabk() {
    int g = blockIdx.x, tid = threadIdx.x;
    __shared__ float red[8];
    float m = -1e30f;
    #pragma unroll
    for (int j=0;j<8;j++) m = fmaxf(m, g_stabq[g*2048 + tid + j*256]);
    #pragma unroll
    for (int o=16;o;o>>=1) m = fmaxf(m, __shfl_xor_sync(~0u,m,o));
    if ((tid&31)==0) red[tid>>5] = m;
    __syncthreads();
    if (tid==0){
        float t = red[0];
        #pragma unroll
        for (int i=1;i<8;i++) t = fmaxf(t, red[i]);
        g_stabk[g] = t;
    }
}

__global__ void k_scale() {
    int r = blockIdx.x*256 + threadIdx.x;
    g_scale[r] = RATIO * __expf(g_stabq[r] - g_stabk[r>>11]);
}

// ---------------- ctx[g] = kp^T @ h, split over N chunks, atomic accumulate ----------------
__global__ void k_ctx() {
    __shared__ float es[32][128];
    __shared__ float hs[32][64];
    int tid = threadIdx.x, tx = tid&15, ty = tid>>4;
    int g = blockIdx.y, mbase = blockIdx.x*128, nch = blockIdx.z;
    size_t ebase = (size_t)g*2048*256;
    const float* hb = g_h + (size_t)g*2048*64;
    float acc[8][4] = {};
    int nend = nch*256 + 256;
    for (int n0=nch*256; n0<nend; n0+=32) {
        #pragma unroll
        for (int t=0;t<4;t++){
            int q = tid + t*256; int kk = q>>5, mq = q&31;
            float sc = g_scale[g*2048 + n0 + kk];
            float4 v = *(const float4*)&g_u[ebase + (size_t)(n0+kk)*256 + mbase + mq*4];
            es[kk][mq*4+0]=fmaf(v.x,sc,REPS); es[kk][mq*4+1]=fmaf(v.y,sc,REPS);
            es[kk][mq*4+2]=fmaf(v.z,sc,REPS); es[kk][mq*4+3]=fmaf(v.w,sc,REPS);
        }
        #pragma unroll
        for (int t=0;t<2;t++){
            int q = tid + t*256; int kk = q>>4, dq = q&15;
            *(float4*)&hs[kk][dq*4] = *(const float4*)&hb[(n0+kk)*64 + dq*4];
        }
        __syncthreads();
        #pragma unroll
        for (int k=0;k<32;k++){
            float a[8], bv[4];
            #pragma unroll
            for (int i=0;i<8;i++) a[i]=es[k][ty*8+i];
            #pragma unroll
            for (int j=0;j<4;j++) bv[j]=hs[k][tx*4+j];
            #pragma unroll
            for (int i=0;i<8;i++)
                #pragma unroll
                for (int j=0;j<4;j++) acc[i][j]=fmaf(a[i],bv[j],acc[i][j]);
        }
        __syncthreads();
    }
    #pragma unroll
    for (int i=0;i<8;i++)
        #pragma unroll
        for (int j=0;j<4;j++)
            atomicAdd(&g_ctx[(g*256 + mbase + ty*8+i)*64 + tx*4+j], acc[i][j]);
}

// ---------------- ksum ----------------
__global__ void k_ksum_init() {
    g_ksum[blockIdx.x*256 + threadIdx.x] = 2048.f * REPS;
}
__global__ void k_ksum() {
    int g = blockIdx.x, nc = blockIdx.y, m = threadIdx.x;
    __shared__ float sc[256];
    sc[m] = g_scale[g*2048 + nc*256 + m];
    __syncthreads();
    const float* e = g_u + ((size_t)(g*2048 + nc*256))*256 + m;
    float acc = 0.f;
    #pragma unroll 4
    for (int n=0; n<256; n++) acc = fmaf(e[(size_t)n*256], sc[n], acc);
    atomicAdd(&g_ksum[g*256 + m], acc);
}

// ---------------- attn = (qp @ ctx) / (qp . ksum); x1 = x + attn ----------------
__global__ void k_attn(const float* __restrict__ x) {
    __shared__ float qs[32][128];
    __shared__ float cs[32][64];
    __shared__ float ks[32];
    __shared__ float sden[128];
    int tid = threadIdx.x, tx = tid&15, ty = tid>>4;
    int g = blockIdx.y, nbase = blockIdx.x*128;
    size_t ebase = (size_t)g*2048*256;
    float acc[8][4] = {}, den[8] = {};
    for (int m0=0; m0<256; m0+=32) {
        #pragma unroll
        for (int t=0;t<4;t++){
            int q = tid + t*256; int nn = q>>3, cq = q&7;
            float4 v = *(const float4*)&g_u[ebase + (size_t)(nbase+nn)*256 + m0 + cq*4];
            qs[cq*4+0][nn]=fmaf(v.x,RATIO,REPS); qs[cq*4+1][nn]=fmaf(v.y,RATIO,REPS);
            qs[cq*4+2][nn]=fmaf(v.z,RATIO,REPS); qs[cq*4+3][nn]=fmaf(v.w,RATIO,REPS);
        }
        #pragma unroll
        for (int t=0;t<2;t++){
            int q = tid + t*256; int kk = q>>4, dq = q&15;
            *(float4*)&cs[kk][dq*4] = *(const float4*)&g_ctx[(g*256 + m0 + kk)*64 + dq*4];
        }
        if (tid < 32) ks[tid] = g_ksum[g*256 + m0 + tid];
        __syncthreads();
        #pragma unroll
        for (int k=0;k<32;k++){
            float a[8], bv[4];
            #pragma unroll
            for (int i=0;i<8;i++) a[i]=qs[k][ty*8+i];
            #pragma unroll
            for (int j=0;j<4;j++) bv[j]=cs[k][tx*4+j];
            #pragma unroll
            for (int i=0;i<8;i++)
                #pragma unroll
                for (int j=0;j<4;j++) acc[i][j]=fmaf(a[i],bv[j],acc[i][j]);
            if (tx==0){
                #pragma unroll
                for (int i=0;i<8;i++) den[i]=fmaf(a[i],ks[k],den[i]);
            }
        }
        __syncthreads();
    }
    if (tx==0){
        #pragma unroll
        for (int i=0;i<8;i++) sden[ty*8+i] = den[i];
    }
    __syncthreads();
    int bb = g/12, hd = g%12;
    #pragma unroll
    for (int i=0;i<8;i++){
        float dinv = 1.f / sden[ty*8+i];
        int n = nbase + ty*8 + i;
        #pragma unroll
        for (int j=0;j<4;j++){
            size_t xi = ((size_t)(bb*2048 + n))*768 + hd*64 + tx*4 + j;
            g_x1[xi] = x[xi] + acc[i][j]*dinv;
        }
    }
}

// ---------------- transpose + half: in[R x C] -> out[C x R] ----------------
__global__ void k_transposeh(const float* __restrict__ in, __half* __restrict__ out,
                             int R, int C) {
    __shared__ float t[32][33];
    int bx = blockIdx.x*32, by = blockIdx.y*32;
    int x = threadIdx.x, y = threadIdx.y;   // block(32,8)
    #pragma unroll
    for (int i=0;i<32;i+=8)
        t[y+i][x] = in[(size_t)(by+y+i)*C + bx+x];
    __syncthreads();
    #pragma unroll
    for (int i=0;i<32;i+=8)
        out[(size_t)(bx+y+i)*R + by+x] = __float2half(t[x][y+i]);
}

// ================= f16 mma.sync GEMM: C[128 x 128] tiles =================
// A: [Mrows x Kdim] half row-major. Bt: [Ncols x Kdim] half row-major.
// EPI 0: Ch=half(gelu(acc+bias)). EPI 1: C=acc+bias+resid. EPI 2: C=acc.
#define STH 40                        // smem row stride in halves
#define STB 80                        // row stride bytes
#define STW 20                        // row stride words
#define STAGE_A 10240                 // 128 rows * 80 B
#define STAGE   (2*STAGE_A)
#define GSMEM_BYTES (2*STAGE)         // 40960 B

template<int EPI>
__global__ __launch_bounds__(256, 2) void k_gemm_h(
        const __half* __restrict__ A, int lda,
        const __half* __restrict__ Bt, int Kdim,
        const float* __restrict__ bias,
        const float* __restrict__ resid,
        float* __restrict__ C, __half* __restrict__ Ch, int ldc) {
    extern __shared__ __align__(16) char dsm[];
    uint32_t smb = s2u(dsm);
    int tid = threadIdx.x, wid = tid>>5, lane = tid&31;
    int wm = (wid&1)*64, wn = (wid>>1)*32;
    int r = lane>>2, cq = lane&3;

    int rbase = blockIdx.y*128, cbase = blockIdx.x*128;
    const __half* Ag = A  + (size_t)rbase*lda;
    const __half* Bg = Bt + (size_t)cbase*Kdim;
    int KT = Kdim >> 5;

    float acc[4][4][4];
    #pragma unroll
    for (int i=0;i<4;i++)
        #pragma unroll
        for (int j=0;j<4;j++)
            #pragma unroll
            for (int k=0;k<4;k++) acc[i][j][k]=0.f;

    #define LOAD_STAGE(s, kt) do { \
        uint32_t _ab = smb + (uint32_t)((s)*STAGE); \
        uint32_t _bb = _ab + STAGE_A; \
        const __half* _Ag = Ag + (kt)*32; \
        const __half* _Bg = Bg + (kt)*32; \
        _Pragma("unroll") \
        for (int _t=0;_t<2;_t++){ \
            int _q = tid + _t*256; int _r = _q>>2, _c = _q&3; \
            cpasync16(_ab + (uint32_t)(_r*STB + _c*16), _Ag + (size_t)_r*lda  + _c*8); \
            cpasync16(_bb + (uint32_t)(_r*STB + _c*16), _Bg + (size_t)_r*Kdim + _c*8); \
        } \
        asm volatile("cp.async.commit_group;" ::: "memory"); \
    } while(0)

    LOAD_STAGE(0, 0);
    for (int kt=0; kt<KT; kt++){
        int cur = kt & 1;
        if (kt+1 < KT){
            LOAD_STAGE(cur^1, kt+1);
            asm volatile("cp.async.wait_group 1;" ::: "memory");
        } else {
            asm volatile("cp.async.wait_group 0;" ::: "memory");
        }
        __syncthreads();
        const uint32_t* As32 = (const uint32_t*)(dsm + cur*STAGE);
        const uint32_t* Bs32 = (const uint32_t*)(dsm + cur*STAGE + STAGE_A);
        #pragma unroll
        for (int ks=0; ks<2; ks++){
            uint32_t a[4][4], b[4][2];
            #pragma unroll
            for (int mf=0; mf<4; mf++){
                int base = (wm + mf*16 + r)*STW + ks*8 + cq;
                a[mf][0] = As32[base];
                a[mf][1] = As32[base + 8*STW];
                a[mf][2] = As32[base + 4];
                a[mf][3] = As32[base + 8*STW + 4];
            }
            #pragma unroll
            for (int nf=0; nf<4; nf++){
                int nb = (wn + nf*8 + r)*STW + ks*8 + cq;
                b[nf][0] = Bs32[nb];
                b[nf][1] = Bs32[nb + 4];
            }
            #pragma unroll
            for (int mf=0; mf<4; mf++)
                #pragma unroll
                for (int nf=0; nf<4; nf++)
                    mma16(acc[mf][nf], a[mf], b[nf]);
        }
        __syncthreads();
    }
    #undef LOAD_STAGE

    // Epilogue: two 64-row halves staged through smem (stride 132)
    float* stg = (float*)dsm;
    #pragma unroll 1
    for (int h=0; h<2; h++){
        __syncthreads();
        if ((wid&1) == h){
            #pragma unroll
            for (int mf=0; mf<4; mf++)
                #pragma unroll
                for (int nf=0; nf<4; nf++){
                    int row = mf*16 + r, col = wn + nf*8 + 2*cq;
                    *(float2*)&stg[row*132 + col]     = make_float2(acc[mf][nf][0], acc[mf][nf][1]);
                    *(float2*)&stg[(row+8)*132 + col] = make_float2(acc[mf][nf][2], acc[mf][nf][3]);
                }
        }
        __syncthreads();
        #pragma unroll
        for (int t=0;t<8;t++){
            int q = tid + t*256; int row = q>>5, c4 = (q&31)*4;
            float4 v = *(const float4*)&stg[row*132 + c4];
            int col = cbase + c4;
            size_t oi = (size_t)(rbase + h*64 + row)*ldc + col;
            if (EPI == 0){
                v.x += bias[col+0]; v.y += bias[col+1]; v.z += bias[col+2]; v.w += bias[col+3];
                v.x = 0.5f*v.x*(1.f+erff(v.x*0.70710678118654752f));
                v.y = 0.5f*v.y*(1.f+erff(v.y*0.70710678118654752f));
                v.z = 0.5f*v.z*(1.f+erff(v.z*0.70710678118654752f));
                v.w = 0.5f*v.w*(1.f+erff(v.w*0.70710678118654752f));
                __half2 p0 = __floats2half2_rn(v.x, v.y);
                __half2 p1 = __floats2half2_rn(v.z, v.w);
                *reinterpret_cast<__half2*>(Ch + oi)     = p0;
                *reinterpret_cast<__half2*>(Ch + oi + 2) = p1;
            } else if (EPI == 1){
                float4 rv = *(const float4*)&resid[oi];
                v.x += bias[col+0] + rv.x; v.y += bias[col+1] + rv.y;
                v.z += bias[col+2] + rv.z; v.w += bias[col+3] + rv.w;
                *(float4*)&C[oi] = v;
            } else {
                *(float4*)&C[oi] = v;
            }
        }
    }
}

extern "C" void kernel_launch(void* const* d_in, const int* in_sizes, int n_in,
                              void* d_out, int out_size) {
    const float* x    = (const float*)d_in[0];
    const float* proj = (const float*)d_in[1];
    const float* ln1g = (const float*)d_in[2];
    const float* ln1b = (const float*)d_in[3];
    const float* ln2g = (const float*)d_in[4];
    const float* ln2b = (const float*)d_in[5];
    const float* W1   = (const float*)d_in[6];
    const float* b1   = (const float*)d_in[7];
    const float* W2   = (const float*)d_in[8];
    const float* b2   = (const float*)d_in[9];
    float* out = (float*)d_out;

    cudaFuncSetAttribute(k_gemm_h<0>, cudaFuncAttributeMaxDynamicSharedMemorySize, GSMEM_BYTES);
    cudaFuncSetAttribute(k_gemm_h<1>, cudaFuncAttributeMaxDynamicSharedMemorySize, GSMEM_BYTES);
    cudaFuncSetAttribute(k_gemm_h<2>, cudaFuncAttributeMaxDynamicSharedMemorySize, GSMEM_BYTES);

    __half* w1h;  cudaGetSymbolAddress((void**)&w1h,  g_w1h);
    __half* w2h;  cudaGetSymbolAddress((void**)&w2h,  g_w2h);
    __half* h2h;  cudaGetSymbolAddress((void**)&h2h,  g_h2h);
    __half* midh; cudaGetSymbolAddress((void**)&midh, g_midh);
    __half* hsh;  cudaGetSymbolAddress((void**)&hsh,  g_hsh);
    __half* prjh; cudaGetSymbolAddress((void**)&prjh, g_projh);
    float* x1;    cudaGetSymbolAddress((void**)&x1,   g_x1);
    float* u;     cudaGetSymbolAddress((void**)&u,    g_u);
    float* ctxp;  cudaGetSymbolAddress((void**)&ctxp, g_ctx);

    // input-only prep (independent of x)
    k_transposeh<<<dim3(Fq/32, Eq/32), dim3(32,8)>>>(W1, w1h, Eq, Fq);   // W1[768x3072] -> [3072x768]
    k_transposeh<<<dim3(Eq/32, Fq/32), dim3(32,8)>>>(W2, w2h, Fq, Eq);   // W2[3072x768] -> [768x3072]
    k_roundproj<<<Mq*Dhq/256, 256>>>(proj);

    k_ln1<<<BN, Eq>>>(x, ln1g, ln1b);
    // u = hsh @ projh^T : [98304 x 64] @ [64 x 256] on tensor pipe (f16)
    k_gemm_h<2><<<dim3(Mq/128, ROWS/128), 256, GSMEM_BYTES>>>(hsh, Dhq, prjh, Dhq, nullptr, nullptr, u, nullptr, Mq);
    k_stabq_exp<<<ROWS/8, 256>>>();
    k_stabk<<<Bq*Hq, 256>>>();
    k_scale<<<ROWS/256, 256>>>();
    cudaMemsetAsync(ctxp, 0, (size_t)Bq*Hq*Mq*Dhq*sizeof(float));
    k_ksum_init<<<Bq*Hq, 256>>>();
    k_ctx<<<dim3(2, Bq*Hq, 8), 256>>>();
    k_ksum<<<dim3(Bq*Hq, 8), 256>>>();
    k_attn<<<dim3(Nq/128, Bq*Hq), 256>>>(x);
    k_ln2<<<BN, Eq>>>(ln2g, ln2b);

    // MLP GEMM1: [8192x768]@[768x3072] -> g_midh (gelu, half)
    k_gemm_h<0><<<dim3(Fq/128, BN/128), 256, GSMEM_BYTES>>>(h2h, Eq, w1h, Eq, b1, nullptr, nullptr, midh, Fq);
    // MLP GEMM2: [8192x3072]@[3072x768] + bias + x1 -> out (float)
    k_gemm_h<1><<<dim3(Eq/128, BN/128), 256, GSMEM_BYTES>>>(midh, Fq, w2h, Fq, b2, x1, out, nullptr, Eq);
}

// round 7
// speedup vs baseline: 3.4094x; 1.0136x over previous
#include <cuda_runtime.h>
#include <cuda_fp16.h>
#include <math.h>
#include <stdint.h>

// Shapes (fixed by the problem)
#define Bq 4
#define Nq 2048
#define Eq 768
#define Hq 12
#define Mq 256
#define Dhq 64
#define Fq 3072
#define ROWS (Bq*Hq*Nq)   // 98304
#define BN (Bq*Nq)        // 8192

#define RATIO 0.0625f            // M^-0.5
#define REPS  6.25e-6f           // RATIO * EPS(1e-4)
#define XSCL  0.35355339059327373f  // Dh^-0.25

// Scratch (device globals; allocation-free)
__device__ float  g_h[ROWS*Dhq];      // LN1 out (unscaled), head layout
__device__ __half g_hsh[ROWS*Dhq];    // half(y*XSCL) for u-GEMM A
__device__ __half g_projh[Mq*Dhq];    // half proj
__device__ float  g_u[ROWS*Mq];       // u, then e = exp(u - diag - stabq)
__device__ __half g_qph[ROWS*Mq];     // half(e*RATIO + REPS)
__device__ float  g_diag[ROWS];
__device__ float  g_stabq[ROWS];
__device__ float  g_scale[ROWS];      // 0.0625*exp(stabq - stabk)
__device__ float  g_stabk[Bq*Hq];
__device__ float  g_ctx[Bq*Hq*Mq*Dhq];
__device__ float  g_ksum[Bq*Hq*Mq];
__device__ __half g_ctxTh[Bq*Hq*128*Mq];  // per head: [128 x 256], row d<64 = ctx^T, row 64 = ksum, rest 0
__device__ float  g_x1[BN*Eq];        // x + attn
__device__ __half g_h2h[BN*Eq];       // LN2 out (half)
__device__ __half g_midh[BN*Fq];      // gelu(h2@W1+b1) (half)
__device__ __half g_w1h[Fq*Eq];       // W1^T half
__device__ __half g_w2h[Eq*Fq];       // W2^T half

// ======================= helpers =======================
__device__ __forceinline__ uint32_t s2u(const void* p){
    uint32_t a;
    asm("{ .reg .u64 t; cvta.to.shared.u64 t, %1; cvt.u32.u64 %0, t; }":"=r"(a):"l"(p));
    return a;
}
__device__ __forceinline__ void cpasync16(uint32_t sa, const void* ga){
    asm volatile("cp.async.cg.shared.global [%0], [%1], 16;" :: "r"(sa), "l"(ga));
}
// f16 MMA, f32 accum (sm_80 baseline; valid on plain sm_103 target)
__device__ __forceinline__ void mma16(float* d, const uint32_t* a, const uint32_t* b){
    asm volatile("mma.sync.aligned.m16n8k16.row.col.f32.f16.f16.f32 "
        "{%0,%1,%2,%3}, {%4,%5,%6,%7}, {%8,%9}, {%0,%1,%2,%3};"
        : "+f"(d[0]),"+f"(d[1]),"+f"(d[2]),"+f"(d[3])
        : "r"(a[0]),"r"(a[1]),"r"(a[2]),"r"(a[3]),"r"(b[0]),"r"(b[1]));
}
#define LDSM4(r0,r1,r2,r3,ad) \
    asm volatile("ldmatrix.sync.aligned.m8n8.x4.shared.b16 {%0,%1,%2,%3}, [%4];" \
        : "=r"(r0),"=r"(r1),"=r"(r2),"=r"(r3) : "r"(ad))

// ---------------- LN1 ----------------
__global__ void k_ln1(const float* __restrict__ x, const float* __restrict__ g,
                      const float* __restrict__ b) {
    int row = blockIdx.x;
    int tid = threadIdx.x;          // 768 threads
    float v = x[row*Eq + tid];
    __shared__ float red[48];
    __shared__ float mv[2];
    float s1 = v, s2 = v*v;
    #pragma unroll
    for (int o=16;o;o>>=1){ s1+=__shfl_xor_sync(~0u,s1,o); s2+=__shfl_xor_sync(~0u,s2,o); }
    int w = tid>>5, l = tid&31;
    if (l==0){ red[w]=s1; red[24+w]=s2; }
    __syncthreads();
    if (tid<32){
        float a = tid<24 ? red[tid]    : 0.f;
        float c = tid<24 ? red[24+tid] : 0.f;
        #pragma unroll
        for (int o=16;o;o>>=1){ a+=__shfl_xor_sync(~0u,a,o); c+=__shfl_xor_sync(~0u,c,o); }
        if (tid==0){ float m=a*(1.f/Eq); mv[0]=m; mv[1]=rsqrtf(c*(1.f/Eq)-m*m+1e-5f); }
    }
    __syncthreads();
    float y = (v - mv[0]) * mv[1] * g[tid] + b[tid];
    int bb = row>>11, n = row&2047, hd = tid>>6, d = tid&63;
    size_t hidx = ((size_t)(bb*Hq+hd)*Nq + n)*Dhq + d;
    g_h[hidx]   = y;
    g_hsh[hidx] = __float2half(y * XSCL);
    __shared__ float sdg[Hq];
    if (tid < Hq) sdg[tid] = 0.f;
    __syncthreads();
    float yy = y*y;
    #pragma unroll
    for (int o=16;o;o>>=1) yy += __shfl_xor_sync(~0u,yy,o);
    if (l==0) atomicAdd(&sdg[w>>1], yy);
    __syncthreads();
    if (tid < Hq) g_diag[(bb*Hq+tid)*Nq + n] = 0.0625f * sdg[tid];
}

// ---------------- LN2 ----------------
__global__ void k_ln2(const float* __restrict__ g, const float* __restrict__ b) {
    int row = blockIdx.x;
    int tid = threadIdx.x;
    float v = g_x1[row*Eq + tid];
    __shared__ float red[48];
    __shared__ float mv[2];
    float s1 = v, s2 = v*v;
    #pragma unroll
    for (int o=16;o;o>>=1){ s1+=__shfl_xor_sync(~0u,s1,o); s2+=__shfl_xor_sync(~0u,s2,o); }
    int w = tid>>5, l = tid&31;
    if (l==0){ red[w]=s1; red[24+w]=s2; }
    __syncthreads();
    if (tid<32){
        float a = tid<24 ? red[tid]    : 0.f;
        float c = tid<24 ? red[24+tid] : 0.f;
        #pragma unroll
        for (int o=16;o;o>>=1){ a+=__shfl_xor_sync(~0u,a,o); c+=__shfl_xor_sync(~0u,c,o); }
        if (tid==0){ float m=a*(1.f/Eq); mv[0]=m; mv[1]=rsqrtf(c*(1.f/Eq)-m*m+1e-5f); }
    }
    __syncthreads();
    g_h2h[row*Eq + tid] = __float2half((v - mv[0]) * mv[1] * g[tid] + b[tid]);
}

__global__ void k_roundproj(const float* __restrict__ proj) {
    int i = blockIdx.x*256 + threadIdx.x;
    g_projh[i] = __float2half(proj[i]);
}

// ---------------- fused: row max + e = exp(u-diag-stabq) + qp half ----------------
__global__ void k_stabq_exp() {
    int row = blockIdx.x*8 + (threadIdx.x>>5);
    int l = threadIdx.x & 31;
    float* u = g_u + (size_t)row*256;
    __half* qp = g_qph + (size_t)row*256;
    float v[8];
    float m = -1e30f;
    #pragma unroll
    for (int j=0;j<8;j++){ v[j] = u[l + j*32]; m = fmaxf(m, v[j]); }
    #pragma unroll
    for (int o=16;o;o>>=1) m = fmaxf(m, __shfl_xor_sync(~0u,m,o));
    if (l==0) g_stabq[row] = m;
    float d = g_diag[row] + m;
    #pragma unroll
    for (int j=0;j<8;j++){
        float e = __expf(v[j] - d);
        u[l + j*32] = e;
        qp[l + j*32] = __float2half(fmaf(e, RATIO, REPS));
    }
}

// ---------------- per-head max (stab_k) ----------------
__global__ void k_stabk() {
    int g = blockIdx.x, tid = threadIdx.x;
    __shared__ float red[8];
    float m = -1e30f;
    #pragma unroll
    for (int j=0;j<8;j++) m = fmaxf(m, g_stabq[g*2048 + tid + j*256]);
    #pragma unroll
    for (int o=16;o;o>>=1) m = fmaxf(m, __shfl_xor_sync(~0u,m,o));
    if ((tid&31)==0) red[tid>>5] = m;
    __syncthreads();
    if (tid==0){
        float t = red[0];
        #pragma unroll
        for (int i=1;i<8;i++) t = fmaxf(t, red[i]);
        g_stabk[g] = t;
    }
}

__global__ void k_scale() {
    int r = blockIdx.x*256 + threadIdx.x;
    g_scale[r] = RATIO * __expf(g_stabq[r] - g_stabk[r>>11]);
}

__global__ void k_ksum_init() {
    g_ksum[blockIdx.x*256 + threadIdx.x] = 0.f;
}

// ---------------- ctx = kp^T @ h (split-N, atomic) + fused ksum ----------------
__global__ void k_ctx() {
    __shared__ float es[32][128];
    __shared__ float hs[32][64];
    int tid = threadIdx.x, tx = tid&15, ty = tid>>4;
    int g = blockIdx.y, mbase = blockIdx.x*128, nch = blockIdx.z;
    size_t ebase = (size_t)g*2048*256;
    const float* hb = g_h + (size_t)g*2048*64;
    float acc[8][4] = {}, den[8] = {};
    int nend = nch*256 + 256;
    for (int n0=nch*256; n0<nend; n0+=32) {
        #pragma unroll
        for (int t=0;t<4;t++){
            int q = tid + t*256; int kk = q>>5, mq = q&31;
            float sc = g_scale[g*2048 + n0 + kk];
            float4 v = *(const float4*)&g_u[ebase + (size_t)(n0+kk)*256 + mbase + mq*4];
            es[kk][mq*4+0]=fmaf(v.x,sc,REPS); es[kk][mq*4+1]=fmaf(v.y,sc,REPS);
            es[kk][mq*4+2]=fmaf(v.z,sc,REPS); es[kk][mq*4+3]=fmaf(v.w,sc,REPS);
        }
        #pragma unroll
        for (int t=0;t<2;t++){
            int q = tid + t*256; int kk = q>>4, dq = q&15;
            *(float4*)&hs[kk][dq*4] = *(const float4*)&hb[(n0+kk)*64 + dq*4];
        }
        __syncthreads();
        #pragma unroll
        for (int k=0;k<32;k++){
            float a[8], bv[4];
            #pragma unroll
            for (int i=0;i<8;i++) a[i]=es[k][ty*8+i];
            #pragma unroll
            for (int j=0;j<4;j++) bv[j]=hs[k][tx*4+j];
            #pragma unroll
            for (int i=0;i<8;i++)
                #pragma unroll
                for (int j=0;j<4;j++) acc[i][j]=fmaf(a[i],bv[j],acc[i][j]);
        }
        if (tx==0){
            #pragma unroll
            for (int k=0;k<32;k++)
                #pragma unroll
                for (int i=0;i<8;i++) den[i] += es[k][ty*8+i];
        }
        __syncthreads();
    }
    #pragma unroll
    for (int i=0;i<8;i++)
        #pragma unroll
        for (int j=0;j<4;j++)
            atomicAdd(&g_ctx[(g*256 + mbase + ty*8+i)*64 + tx*4+j], acc[i][j]);
    if (tx==0){
        #pragma unroll
        for (int i=0;i<8;i++)
            atomicAdd(&g_ksum[g*256 + mbase + ty*8+i], den[i]);
    }
}

// ---------------- build ctxTh: [g][d][m] half (d<64), via 32x32 tiles ----------------
__global__ void k_ctxh() {
    __shared__ float t[32][33];
    int db = blockIdx.x*32, mb = blockIdx.y*32, g = blockIdx.z;
    int x = threadIdx.x, y = threadIdx.y;   // block (32, 8)
    #pragma unroll
    for (int i=0;i<32;i+=8)
        t[y+i][x] = g_ctx[(g*256 + mb + y+i)*64 + db + x];   // t[m_local][d_local]
    __syncthreads();
    #pragma unroll
    for (int i=0;i<32;i+=8)
        g_ctxTh[(size_t)g*128*256 + (db + y+i)*256 + mb + x] = __float2half(t[x][y+i]);
}
// ksum row (64) + zero rows 65..127
__global__ void k_ctxh2() {
    int g = blockIdx.x, tid = threadIdx.x;   // 256 threads
    __half* base = g_ctxTh + (size_t)g*128*256;
    base[64*256 + tid] = __float2half(g_ksum[g*256 + tid]);
    for (int r=65; r<128; r++) base[r*256 + tid] = __float2half(0.f);
}

// ---------------- transpose weights to half ----------------
__global__ void k_transposeh(const float* __restrict__ in, __half* __restrict__ out,
                             int R, int C) {
    __shared__ float t[32][33];
    int bx = blockIdx.x*32, by = blockIdx.y*32;
    int x = threadIdx.x, y = threadIdx.y;   // block(32,8)
    #pragma unroll
    for (int i=0;i<32;i+=8)
        t[y+i][x] = in[(size_t)(by+y+i)*C + bx+x];
    __syncthreads();
    #pragma unroll
    for (int i=0;i<32;i+=8)
        out[(size_t)(bx+y+i)*R + by+x] = __float2half(t[x][y+i]);
}

// ================= f16 mma.sync GEMM with ldmatrix: C[128 x 128] tiles =================
// A: [z*strA + Mrows x Kdim] half row-major. Bt: [z*strB + Ncols x Kdim] half row-major.
// EPI 0: Ch=half(gelu(acc+bias)). EPI 1: C=acc+bias+resid. EPI 2: C=acc.
// EPI 3: attention epilogue: per head z, col 64 = denominator; out = resid + num/den into C.
#define STB 80                        // smem row stride bytes (40 halves)
#define STAGE_A 10240                 // 128 rows * 80 B
#define STAGE   (2*STAGE_A)
#define GSMEM_BYTES (2*STAGE)         // 40960 B

template<int EPI>
__global__ __launch_bounds__(256, 2) void k_gemm_h(
        const __half* __restrict__ A, int lda, size_t strA,
        const __half* __restrict__ Bt, int Kdim, size_t strB,
        const float* __restrict__ bias,
        const float* __restrict__ resid,
        float* __restrict__ C, __half* __restrict__ Ch, int ldc) {
    extern __shared__ __align__(16) char dsm[];
    uint32_t smb = s2u(dsm);
    int tid = threadIdx.x, wid = tid>>5, lane = tid&31;
    int wm = (wid&1)*64, wn = (wid>>1)*32;
    int r = lane>>2, cq = lane&3;
    int z = blockIdx.z;

    int rbase = blockIdx.y*128, cbase = blockIdx.x*128;
    const __half* Ag = A  + z*strA + (size_t)rbase*lda;
    const __half* Bg = Bt + z*strB + (size_t)cbase*Kdim;
    int KT = Kdim >> 5;

    // ldmatrix base addresses (per warp)
    uint32_t a_ldsm_base = (uint32_t)((wm + (lane&7) + ((lane>>3)&1)*8)*STB + ((lane>>4)&1)*16);
    uint32_t b_ldsm_base = (uint32_t)((wn + (lane&7) + ((lane>>4)&1)*8)*STB + ((lane>>3)&1)*16);

    float acc[4][4][4];
    #pragma unroll
    for (int i=0;i<4;i++)
        #pragma unroll
        for (int j=0;j<4;j++)
            #pragma unroll
            for (int k=0;k<4;k++) acc[i][j][k]=0.f;

    #define LOAD_STAGE(s, kt) do { \
        uint32_t _ab = smb + (uint32_t)((s)*STAGE); \
        uint32_t _bb = _ab + STAGE_A; \
        const __half* _Ag = Ag + (kt)*32; \
        const __half* _Bg = Bg + (kt)*32; \
        _Pragma("unroll") \
        for (int _t=0;_t<2;_t++){ \
            int _q = tid + _t*256; int _r = _q>>2, _c = _q&3; \
            cpasync16(_ab + (uint32_t)(_r*STB + _c*16), _Ag + (size_t)_r*lda  + _c*8); \
            cpasync16(_bb + (uint32_t)(_r*STB + _c*16), _Bg + (size_t)_r*Kdim + _c*8); \
        } \
        asm volatile("cp.async.commit_group;" ::: "memory"); \
    } while(0)

    LOAD_STAGE(0, 0);
    for (int kt=0; kt<KT; kt++){
        int cur = kt & 1;
        if (kt+1 < KT){
            LOAD_STAGE(cur^1, kt+1);
            asm volatile("cp.async.wait_group 1;" ::: "memory");
        } else {
            asm volatile("cp.async.wait_group 0;" ::: "memory");
        }
        __syncthreads();
        uint32_t ab = smb + (uint32_t)(cur*STAGE) + a_ldsm_base;
        uint32_t bb = smb + (uint32_t)(cur*STAGE) + STAGE_A + b_ldsm_base;
        #pragma unroll
        for (int ks=0; ks<2; ks++){
            uint32_t a[4][4], b[2][4];
            #pragma unroll
            for (int mf=0; mf<4; mf++)
                LDSM4(a[mf][0],a[mf][1],a[mf][2],a[mf][3], ab + mf*16*STB + ks*32);
            #pragma unroll
            for (int p=0; p<2; p++)
                LDSM4(b[p][0],b[p][1],b[p][2],b[p][3], bb + p*16*STB + ks*32);
            #pragma unroll
            for (int mf=0; mf<4; mf++)
                #pragma unroll
                for (int nf=0; nf<4; nf++)
                    mma16(acc[mf][nf], a[mf], &b[nf>>1][(nf&1)*2]);
        }
        __syncthreads();
    }
    #undef LOAD_STAGE

    // Epilogue: two 64-row halves staged through smem (stride 132)
    float* stg = (float*)dsm;
    #pragma unroll 1
    for (int h=0; h<2; h++){
        __syncthreads();
        if ((wid&1) == h){
            #pragma unroll
            for (int mf=0; mf<4; mf++)
                #pragma unroll
                for (int nf=0; nf<4; nf++){
                    int row = mf*16 + r, col = wn + nf*8 + 2*cq;
                    *(float2*)&stg[row*132 + col]     = make_float2(acc[mf][nf][0], acc[mf][nf][1]);
                    *(float2*)&stg[(row+8)*132 + col] = make_float2(acc[mf][nf][2], acc[mf][nf][3]);
                }
        }
        __syncthreads();
        #pragma unroll
        for (int t=0;t<8;t++){
            int q = tid + t*256; int row = q>>5, c4 = (q&31)*4;
            int col = cbase + c4;
            if (EPI == 3){
                if (c4 < 64){
                    float4 v = *(const float4*)&stg[row*132 + c4];
                    float dinv = 1.f / stg[row*132 + 64];
                    int bb2 = z/12, hd = z%12;
                    int n = rbase + h*64 + row;
                    size_t oi = ((size_t)(bb2*2048 + n))*768 + hd*64 + c4;
                    float4 rv = *(const float4*)&resid[oi];
                    v.x = rv.x + v.x*dinv; v.y = rv.y + v.y*dinv;
                    v.z = rv.z + v.z*dinv; v.w = rv.w + v.w*dinv;
                    *(float4*)&C[oi] = v;
                }
            } else {
                float4 v = *(const float4*)&stg[row*132 + c4];
                size_t oi = (size_t)(rbase + h*64 + row)*ldc + col;
                if (EPI == 0){
                    v.x += bias[col+0]; v.y += bias[col+1]; v.z += bias[col+2]; v.w += bias[col+3];
                    v.x = 0.5f*v.x*(1.f+erff(v.x*0.70710678118654752f));
                    v.y = 0.5f*v.y*(1.f+erff(v.y*0.70710678118654752f));
                    v.z = 0.5f*v.z*(1.f+erff(v.z*0.70710678118654752f));
                    v.w = 0.5f*v.w*(1.f+erff(v.w*0.70710678118654752f));
                    __half2 p0 = __floats2half2_rn(v.x, v.y);
                    __half2 p1 = __floats2half2_rn(v.z, v.w);
                    *reinterpret_cast<__half2*>(Ch + oi)     = p0;
                    *reinterpret_cast<__half2*>(Ch + oi + 2) = p1;
                } else if (EPI == 1){
                    float4 rv = *(const float4*)&resid[oi];
                    v.x += bias[col+0] + rv.x; v.y += bias[col+1] + rv.y;
                    v.z += bias[col+2] + rv.z; v.w += bias[col+3] + rv.w;
                    *(float4*)&C[oi] = v;
                } else {
                    *(float4*)&C[oi] = v;
                }
            }
        }
    }
}

extern "C" void kernel_launch(void* const* d_in, const int* in_sizes, int n_in,
                              void* d_out, int out_size) {
    const float* x    = (const float*)d_in[0];
    const float* proj = (const float*)d_in[1];
    const float* ln1g = (const float*)d_in[2];
    const float* ln1b = (const float*)d_in[3];
    const float* ln2g = (const float*)d_in[4];
    const float* ln2b = (const float*)d_in[5];
    const float* W1   = (const float*)d_in[6];
    const float* b1   = (const float*)d_in[7];
    const float* W2   = (const float*)d_in[8];
    const float* b2   = (const float*)d_in[9];
    float* out = (float*)d_out;

    cudaFuncSetAttribute(k_gemm_h<0>, cudaFuncAttributeMaxDynamicSharedMemorySize, GSMEM_BYTES);
    cudaFuncSetAttribute(k_gemm_h<1>, cudaFuncAttributeMaxDynamicSharedMemorySize, GSMEM_BYTES);
    cudaFuncSetAttribute(k_gemm_h<2>, cudaFuncAttributeMaxDynamicSharedMemorySize, GSMEM_BYTES);
    cudaFuncSetAttribute(k_gemm_h<3>, cudaFuncAttributeMaxDynamicSharedMemorySize, GSMEM_BYTES);

    __half* w1h;  cudaGetSymbolAddress((void**)&w1h,  g_w1h);
    __half* w2h;  cudaGetSymbolAddress((void**)&w2h,  g_w2h);
    __half* h2h;  cudaGetSymbolAddress((void**)&h2h,  g_h2h);
    __half* midh; cudaGetSymbolAddress((void**)&midh, g_midh);
    __half* hsh;  cudaGetSymbolAddress((void**)&hsh,  g_hsh);
    __half* prjh; cudaGetSymbolAddress((void**)&prjh, g_projh);
    __half* qph;  cudaGetSymbolAddress((void**)&qph,  g_qph);
    __half* ctxh; cudaGetSymbolAddress((void**)&ctxh, g_ctxTh);
    float* x1;    cudaGetSymbolAddress((void**)&x1,   g_x1);
    float* u;     cudaGetSymbolAddress((void**)&u,    g_u);
    float* ctxp;  cudaGetSymbolAddress((void**)&ctxp, g_ctx);

    // input-only prep
    k_transposeh<<<dim3(Fq/32, Eq/32), dim3(32,8)>>>(W1, w1h, Eq, Fq);
    k_transposeh<<<dim3(Eq/32, Fq/32), dim3(32,8)>>>(W2, w2h, Fq, Eq);
    k_roundproj<<<Mq*Dhq/256, 256>>>(proj);

    k_ln1<<<BN, Eq>>>(x, ln1g, ln1b);
    // u = hsh @ projh^T : [98304 x 64] @ [64 x 256]
    k_gemm_h<2><<<dim3(Mq/128, ROWS/128), 256, GSMEM_BYTES>>>(hsh, Dhq, 0, prjh, Dhq, 0, nullptr, nullptr, u, nullptr, Mq);
    k_stabq_exp<<<ROWS/8, 256>>>();
    k_stabk<<<Bq*Hq, 256>>>();
    k_scale<<<ROWS/256, 256>>>();
    cudaMemsetAsync(ctxp, 0, (size_t)Bq*Hq*Mq*Dhq*sizeof(float));
    k_ksum_init<<<Bq*Hq, 256>>>();
    k_ctx<<<dim3(2, Bq*Hq, 8), 256>>>();
    k_ctxh<<<dim3(2, 8, Bq*Hq), dim3(32,8)>>>();
    k_ctxh2<<<Bq*Hq, 256>>>();
    // attn: per head [2048 x 256] @ [256 x 128(ctx^T|ksum|0)] -> x1 = x + num/den
    k_gemm_h<3><<<dim3(1, Nq/128, Bq*Hq), 256, GSMEM_BYTES>>>(
        qph, Mq, (size_t)Nq*Mq, ctxh, Mq, (size_t)128*Mq, nullptr, x, x1, nullptr, 0);
    k_ln2<<<BN, Eq>>>(ln2g, ln2b);

    // MLP GEMM1: [8192x768]@[768x3072] -> midh (gelu, half)
    k_gemm_h<0><<<dim3(Fq/128, BN/128), 256, GSMEM_BYTES>>>(h2h, Eq, 0, w1h, Eq, 0, b1, nullptr, nullptr, midh, Fq);
    // MLP GEMM2: [8192x3072]@[3072x768] + bias + x1 -> out
    k_gemm_h<1><<<dim3(Eq/128, BN/128), 256, GSMEM_BYTES>>>(midh, Fq, 0, w2h, Fq, 0, b2, x1, out, nullptr, Eq);
}

// round 8
// speedup vs baseline: 3.7338x; 1.0951x over previous
#include <cuda_runtime.h>
#include <cuda_fp16.h>
#include <math.h>
#include <stdint.h>

// Shapes (fixed by the problem)
#define Bq 4
#define Nq 2048
#define Eq 768
#define Hq 12
#define Mq 256
#define Dhq 64
#define Fq 3072
#define ROWS (Bq*Hq*Nq)   // 98304
#define BN (Bq*Nq)        // 8192

#define RATIO 0.0625f            // M^-0.5
#define REPS  6.25e-6f           // RATIO * EPS(1e-4)
#define XSCL  0.35355339059327373f  // Dh^-0.25

// Scratch (device globals; allocation-free)
__device__ float  g_h[ROWS*Dhq];      // LN1 out (unscaled), head layout
__device__ __half g_hsh[ROWS*Dhq];    // half(y*XSCL) for u-GEMM A
__device__ __half g_projh[Mq*Dhq];    // half proj
__device__ float  g_u[ROWS*Mq];       // u, then e = exp(u - diag - stabq)
__device__ __half g_qph[ROWS*Mq];     // half(e*RATIO + REPS)
__device__ float  g_diag[ROWS];
__device__ float  g_stabq[ROWS];
__device__ float  g_scale[ROWS];      // 0.0625*exp(stabq - stabk)
__device__ float  g_stabk[Bq*Hq];
__device__ float  g_ctx[Bq*Hq*Mq*Dhq];
__device__ float  g_ksum[Bq*Hq*Mq];
__device__ __half g_ctxTh[Bq*Hq*128*Mq];  // per head: [128 x 256], d<64 = ctx^T, row 64 = ksum, rest 0
__device__ float  g_x1[BN*Eq];        // x + attn
__device__ __half g_h2h[BN*Eq];       // LN2 out (half)
__device__ __half g_midh[BN*Fq];      // gelu(h2@W1+b1) (half)
__device__ __half g_w1h[Fq*Eq];       // W1^T half
__device__ __half g_w2h[Eq*Fq];       // W2^T half

// ======================= helpers =======================
__device__ __forceinline__ uint32_t s2u(const void* p){
    uint32_t a;
    asm("{ .reg .u64 t; cvta.to.shared.u64 t, %1; cvt.u32.u64 %0, t; }":"=r"(a):"l"(p));
    return a;
}
__device__ __forceinline__ void cpasync16(uint32_t sa, const void* ga){
    asm volatile("cp.async.cg.shared.global [%0], [%1], 16;" :: "r"(sa), "l"(ga));
}
__device__ __forceinline__ void mma16(float* d, const uint32_t* a, const uint32_t* b){
    asm volatile("mma.sync.aligned.m16n8k16.row.col.f32.f16.f16.f32 "
        "{%0,%1,%2,%3}, {%4,%5,%6,%7}, {%8,%9}, {%0,%1,%2,%3};"
        : "+f"(d[0]),"+f"(d[1]),"+f"(d[2]),"+f"(d[3])
        : "r"(a[0]),"r"(a[1]),"r"(a[2]),"r"(a[3]),"r"(b[0]),"r"(b[1]));
}
#define LDSM4(r0,r1,r2,r3,ad) \
    asm volatile("ldmatrix.sync.aligned.m8n8.x4.shared.b16 {%0,%1,%2,%3}, [%4];" \
        : "=r"(r0),"=r"(r1),"=r"(r2),"=r"(r3) : "r"(ad))

// ---------------- LN1: warp-per-token, shfl-only ----------------
__global__ void k_ln1(const float* __restrict__ x, const float* __restrict__ g,
                      const float* __restrict__ b) {
    int warp = (blockIdx.x*256 + threadIdx.x) >> 5;   // token 0..8191
    int l = threadIdx.x & 31;
    const float4* xr = (const float4*)(x + (size_t)warp*Eq);
    float4 v[6];
    float s1 = 0.f, s2 = 0.f;
    #pragma unroll
    for (int i=0;i<6;i++){
        v[i] = xr[l + 32*i];
        s1 += v[i].x+v[i].y+v[i].z+v[i].w;
        s2 += v[i].x*v[i].x+v[i].y*v[i].y+v[i].z*v[i].z+v[i].w*v[i].w;
    }
    #pragma unroll
    for (int o=16;o;o>>=1){ s1+=__shfl_xor_sync(~0u,s1,o); s2+=__shfl_xor_sync(~0u,s2,o); }
    float m = s1*(1.f/Eq);
    float rstd = rsqrtf(s2*(1.f/Eq) - m*m + 1e-5f);
    int bb = warp>>11, n = warp&2047;
    #pragma unroll
    for (int i=0;i<6;i++){
        int f = l + 32*i;          // float4 index in row
        int e = f*4;               // element index
        float4 gv = ((const float4*)g)[f];
        float4 bv = ((const float4*)b)[f];
        float4 y;
        y.x = (v[i].x-m)*rstd*gv.x + bv.x;
        y.y = (v[i].y-m)*rstd*gv.y + bv.y;
        y.z = (v[i].z-m)*rstd*gv.z + bv.z;
        y.w = (v[i].w-m)*rstd*gv.w + bv.w;
        int hd = e>>6, d = e&63;
        size_t hi = ((size_t)(bb*Hq+hd)*Nq + n)*Dhq + d;
        *(float4*)&g_h[hi] = y;
        *(__half2*)&g_hsh[hi]   = __floats2half2_rn(y.x*XSCL, y.y*XSCL);
        *(__half2*)&g_hsh[hi+2] = __floats2half2_rn(y.z*XSCL, y.w*XSCL);
        float yy = y.x*y.x + y.y*y.y + y.z*y.z + y.w*y.w;
        #pragma unroll
        for (int o=8;o;o>>=1) yy += __shfl_xor_sync(~0u,yy,o);
        if ((l&15)==0){
            int hd2 = 2*i + (l>>4);
            g_diag[(bb*Hq+hd2)*Nq + n] = 0.0625f * yy;
        }
    }
}

// ---------------- LN2: warp-per-token, half out ----------------
__global__ void k_ln2(const float* __restrict__ g, const float* __restrict__ b) {
    int warp = (blockIdx.x*256 + threadIdx.x) >> 5;
    int l = threadIdx.x & 31;
    const float4* xr = (const float4*)(g_x1 + (size_t)warp*Eq);
    float4 v[6];
    float s1 = 0.f, s2 = 0.f;
    #pragma unroll
    for (int i=0;i<6;i++){
        v[i] = xr[l + 32*i];
        s1 += v[i].x+v[i].y+v[i].z+v[i].w;
        s2 += v[i].x*v[i].x+v[i].y*v[i].y+v[i].z*v[i].z+v[i].w*v[i].w;
    }
    #pragma unroll
    for (int o=16;o;o>>=1){ s1+=__shfl_xor_sync(~0u,s1,o); s2+=__shfl_xor_sync(~0u,s2,o); }
    float m = s1*(1.f/Eq);
    float rstd = rsqrtf(s2*(1.f/Eq) - m*m + 1e-5f);
    __half* hr = g_h2h + (size_t)warp*Eq;
    #pragma unroll
    for (int i=0;i<6;i++){
        int f = l + 32*i;
        float4 gv = ((const float4*)g)[f];
        float4 bv = ((const float4*)b)[f];
        float4 y;
        y.x = (v[i].x-m)*rstd*gv.x + bv.x;
        y.y = (v[i].y-m)*rstd*gv.y + bv.y;
        y.z = (v[i].z-m)*rstd*gv.z + bv.z;
        y.w = (v[i].w-m)*rstd*gv.w + bv.w;
        *(__half2*)&hr[f*4]   = __floats2half2_rn(y.x, y.y);
        *(__half2*)&hr[f*4+2] = __floats2half2_rn(y.z, y.w);
    }
}

__global__ void k_roundproj(const float* __restrict__ proj) {
    int i = blockIdx.x*256 + threadIdx.x;
    g_projh[i] = __float2half(proj[i]);
}

// ---------------- fused: row max + e = exp(u-diag-stabq) + qp half ----------------
__global__ void k_stabq_exp() {
    int row = blockIdx.x*8 + (threadIdx.x>>5);
    int l = threadIdx.x & 31;
    float* u = g_u + (size_t)row*256;
    __half* qp = g_qph + (size_t)row*256;
    float v[8];
    float m = -1e30f;
    #pragma unroll
    for (int j=0;j<8;j++){ v[j] = u[l + j*32]; m = fmaxf(m, v[j]); }
    #pragma unroll
    for (int o=16;o;o>>=1) m = fmaxf(m, __shfl_xor_sync(~0u,m,o));
    if (l==0) g_stabq[row] = m;
    float d = g_diag[row] + m;
    #pragma unroll
    for (int j=0;j<8;j++){
        float e = __expf(v[j] - d);
        u[l + j*32] = e;
        qp[l + j*32] = __float2half(fmaf(e, RATIO, REPS));
    }
}

// ---------------- per-head max (stab_k) ----------------
__global__ void k_stabk() {
    int g = blockIdx.x, tid = threadIdx.x;
    __shared__ float red[8];
    float m = -1e30f;
    #pragma unroll
    for (int j=0;j<8;j++) m = fmaxf(m, g_stabq[g*2048 + tid + j*256]);
    #pragma unroll
    for (int o=16;o;o>>=1) m = fmaxf(m, __shfl_xor_sync(~0u,m,o));
    if ((tid&31)==0) red[tid>>5] = m;
    __syncthreads();
    if (tid==0){
        float t = red[0];
        #pragma unroll
        for (int i=1;i<8;i++) t = fmaxf(t, red[i]);
        g_stabk[g] = t;
    }
}

__global__ void k_scale() {
    int r = blockIdx.x*256 + threadIdx.x;
    g_scale[r] = RATIO * __expf(g_stabq[r] - g_stabk[r>>11]);
}

__global__ void k_ksum_init() {
    g_ksum[blockIdx.x*256 + threadIdx.x] = 0.f;
}

// ---------------- ctx = kp^T @ h (split-N, atomic) + fused ksum ----------------
__global__ void k_ctx() {
    __shared__ float es[32][128];
    __shared__ float hs[32][64];
    int tid = threadIdx.x, tx = tid&15, ty = tid>>4;
    int g = blockIdx.y, mbase = blockIdx.x*128, nch = blockIdx.z;
    size_t ebase = (size_t)g*2048*256;
    const float* hb = g_h + (size_t)g*2048*64;
    float acc[8][4] = {}, den[8] = {};
    int nend = nch*256 + 256;
    for (int n0=nch*256; n0<nend; n0+=32) {
        #pragma unroll
        for (int t=0;t<4;t++){
            int q = tid + t*256; int kk = q>>5, mq = q&31;
            float sc = g_scale[g*2048 + n0 + kk];
            float4 v = *(const float4*)&g_u[ebase + (size_t)(n0+kk)*256 + mbase + mq*4];
            es[kk][mq*4+0]=fmaf(v.x,sc,REPS); es[kk][mq*4+1]=fmaf(v.y,sc,REPS);
            es[kk][mq*4+2]=fmaf(v.z,sc,REPS); es[kk][mq*4+3]=fmaf(v.w,sc,REPS);
        }
        #pragma unroll
        for (int t=0;t<2;t++){
            int q = tid + t*256; int kk = q>>4, dq = q&15;
            *(float4*)&hs[kk][dq*4] = *(const float4*)&hb[(n0+kk)*64 + dq*4];
        }
        __syncthreads();
        #pragma unroll
        for (int k=0;k<32;k++){
            float a[8], bv[4];
            #pragma unroll
            for (int i=0;i<8;i++) a[i]=es[k][ty*8+i];
            #pragma unroll
            for (int j=0;j<4;j++) bv[j]=hs[k][tx*4+j];
            #pragma unroll
            for (int i=0;i<8;i++)
                #pragma unroll
                for (int j=0;j<4;j++) acc[i][j]=fmaf(a[i],bv[j],acc[i][j]);
        }
        if (tx==0){
            #pragma unroll
            for (int k=0;k<32;k++)
                #pragma unroll
                for (int i=0;i<8;i++) den[i] += es[k][ty*8+i];
        }
        __syncthreads();
    }
    #pragma unroll
    for (int i=0;i<8;i++)
        #pragma unroll
        for (int j=0;j<4;j++)
            atomicAdd(&g_ctx[(g*256 + mbase + ty*8+i)*64 + tx*4+j], acc[i][j]);
    if (tx==0){
        #pragma unroll
        for (int i=0;i<8;i++)
            atomicAdd(&g_ksum[g*256 + mbase + ty*8+i], den[i]);
    }
}

// ---------------- build ctxTh ----------------
__global__ void k_ctxh() {
    __shared__ float t[32][33];
    int db = blockIdx.x*32, mb = blockIdx.y*32, g = blockIdx.z;
    int x = threadIdx.x, y = threadIdx.y;   // block (32, 8)
    #pragma unroll
    for (int i=0;i<32;i+=8)
        t[y+i][x] = g_ctx[(g*256 + mb + y+i)*64 + db + x];
    __syncthreads();
    #pragma unroll
    for (int i=0;i<32;i+=8)
        g_ctxTh[(size_t)g*128*256 + (db + y+i)*256 + mb + x] = __float2half(t[x][y+i]);
}
__global__ void k_ctxh2() {
    int g = blockIdx.x, tid = threadIdx.x;
    __half* base = g_ctxTh + (size_t)g*128*256;
    base[64*256 + tid] = __float2half(g_ksum[g*256 + tid]);
    for (int r=65; r<128; r++) base[r*256 + tid] = __float2half(0.f);
}

// ---------------- transpose weights to half ----------------
__global__ void k_transposeh(const float* __restrict__ in, __half* __restrict__ out,
                             int R, int C) {
    __shared__ float t[32][33];
    int bx = blockIdx.x*32, by = blockIdx.y*32;
    int x = threadIdx.x, y = threadIdx.y;
    #pragma unroll
    for (int i=0;i<32;i+=8)
        t[y+i][x] = in[(size_t)(by+y+i)*C + bx+x];
    __syncthreads();
    #pragma unroll
    for (int i=0;i<32;i+=8)
        out[(size_t)(bx+y+i)*R + by+x] = __float2half(t[x][y+i]);
}

// ================= f16 mma.sync GEMM (ldmatrix, 3-stage cp.async) =================
#define STB 80                        // smem row stride bytes (40 halves)
#define STAGE_A 10240                 // 128 rows * 80 B
#define STAGE   (2*STAGE_A)           // 20480
#define GSMEM_BYTES (3*STAGE)         // 61440 B

template<int EPI>
__global__ __launch_bounds__(256, 2) void k_gemm_h(
        const __half* __restrict__ A, int lda, size_t strA,
        const __half* __restrict__ Bt, int Kdim, size_t strB,
        const float* __restrict__ bias,
        const float* __restrict__ resid,
        float* __restrict__ C, __half* __restrict__ Ch, int ldc) {
    extern __shared__ __align__(16) char dsm[];
    uint32_t smb = s2u(dsm);
    int tid = threadIdx.x, wid = tid>>5, lane = tid&31;
    int wm = (wid&1)*64, wn = (wid>>1)*32;
    int r = lane>>2, cq = lane&3;
    int z = blockIdx.z;

    int rbase = blockIdx.y*128, cbase = blockIdx.x*128;
    const __half* Ag = A  + z*strA + (size_t)rbase*lda;
    const __half* Bg = Bt + z*strB + (size_t)cbase*Kdim;
    int KT = Kdim >> 5;

    uint32_t a_ldsm_base = (uint32_t)((wm + (lane&7) + ((lane>>3)&1)*8)*STB + ((lane>>4)&1)*16);
    uint32_t b_ldsm_base = (uint32_t)((wn + (lane&7) + ((lane>>4)&1)*8)*STB + ((lane>>3)&1)*16);

    float acc[4][4][4];
    #pragma unroll
    for (int i=0;i<4;i++)
        #pragma unroll
        for (int j=0;j<4;j++)
            #pragma unroll
            for (int k=0;k<4;k++) acc[i][j][k]=0.f;

    #define LOAD_STAGE(s, kt) do { \
        uint32_t _ab = smb + (uint32_t)((s)*STAGE); \
        uint32_t _bb = _ab + STAGE_A; \
        const __half* _Ag = Ag + (kt)*32; \
        const __half* _Bg = Bg + (kt)*32; \
        _Pragma("unroll") \
        for (int _t=0;_t<2;_t++){ \
            int _q = tid + _t*256; int _r = _q>>2, _c = _q&3; \
            cpasync16(_ab + (uint32_t)(_r*STB + _c*16), _Ag + (size_t)_r*lda  + _c*8); \
            cpasync16(_bb + (uint32_t)(_r*STB + _c*16), _Bg + (size_t)_r*Kdim + _c*8); \
        } \
        asm volatile("cp.async.commit_group;" ::: "memory"); \
    } while(0)

    LOAD_STAGE(0, 0);
    if (KT > 1) LOAD_STAGE(1, 1);
    int cur = 0;
    for (int kt=0; kt<KT; kt++){
        if (kt+2 < KT){
            int nxt = cur+2; if (nxt>=3) nxt-=3;
            LOAD_STAGE(nxt, kt+2);
            asm volatile("cp.async.wait_group 2;" ::: "memory");
        } else if (kt+1 < KT){
            asm volatile("cp.async.wait_group 1;" ::: "memory");
        } else {
            asm volatile("cp.async.wait_group 0;" ::: "memory");
        }
        __syncthreads();
        uint32_t ab = smb + (uint32_t)(cur*STAGE) + a_ldsm_base;
        uint32_t bb = smb + (uint32_t)(cur*STAGE) + STAGE_A + b_ldsm_base;
        #pragma unroll
        for (int ks=0; ks<2; ks++){
            uint32_t a[4][4], b[2][4];
            #pragma unroll
            for (int mf=0; mf<4; mf++)
                LDSM4(a[mf][0],a[mf][1],a[mf][2],a[mf][3], ab + mf*16*STB + ks*32);
            #pragma unroll
            for (int p=0; p<2; p++)
                LDSM4(b[p][0],b[p][1],b[p][2],b[p][3], bb + p*16*STB + ks*32);
            #pragma unroll
            for (int mf=0; mf<4; mf++)
                #pragma unroll
                for (int nf=0; nf<4; nf++)
                    mma16(acc[mf][nf], a[mf], &b[nf>>1][(nf&1)*2]);
        }
        __syncthreads();
        cur = (cur==2) ? 0 : cur+1;
    }
    #undef LOAD_STAGE

    // Epilogue: two 64-row halves staged through smem (stride 132)
    float* stg = (float*)dsm;
    #pragma unroll 1
    for (int h=0; h<2; h++){
        __syncthreads();
        if ((wid&1) == h){
            #pragma unroll
            for (int mf=0; mf<4; mf++)
                #pragma unroll
                for (int nf=0; nf<4; nf++){
                    int row = mf*16 + r, col = wn + nf*8 + 2*cq;
                    *(float2*)&stg[row*132 + col]     = make_float2(acc[mf][nf][0], acc[mf][nf][1]);
                    *(float2*)&stg[(row+8)*132 + col] = make_float2(acc[mf][nf][2], acc[mf][nf][3]);
                }
        }
        __syncthreads();
        #pragma unroll
        for (int t=0;t<8;t++){
            int q = tid + t*256; int row = q>>5, c4 = (q&31)*4;
            int col = cbase + c4;
            if (EPI == 3){
                if (c4 < 64){
                    float4 v = *(const float4*)&stg[row*132 + c4];
                    float dinv = 1.f / stg[row*132 + 64];
                    int bb2 = z/12, hd = z%12;
                    int n = rbase + h*64 + row;
                    size_t oi = ((size_t)(bb2*2048 + n))*768 + hd*64 + c4;
                    float4 rv = *(const float4*)&resid[oi];
                    v.x = rv.x + v.x*dinv; v.y = rv.y + v.y*dinv;
                    v.z = rv.z + v.z*dinv; v.w = rv.w + v.w*dinv;
                    *(float4*)&C[oi] = v;
                }
            } else {
                float4 v = *(const float4*)&stg[row*132 + c4];
                size_t oi = (size_t)(rbase + h*64 + row)*ldc + col;
                if (EPI == 0){
                    v.x += bias[col+0]; v.y += bias[col+1]; v.z += bias[col+2]; v.w += bias[col+3];
                    v.x = 0.5f*v.x*(1.f+erff(v.x*0.70710678118654752f));
                    v.y = 0.5f*v.y*(1.f+erff(v.y*0.70710678118654752f));
                    v.z = 0.5f*v.z*(1.f+erff(v.z*0.70710678118654752f));
                    v.w = 0.5f*v.w*(1.f+erff(v.w*0.70710678118654752f));
                    *reinterpret_cast<__half2*>(Ch + oi)     = __floats2half2_rn(v.x, v.y);
                    *reinterpret_cast<__half2*>(Ch + oi + 2) = __floats2half2_rn(v.z, v.w);
                } else if (EPI == 1){
                    float4 rv = *(const float4*)&resid[oi];
                    v.x += bias[col+0] + rv.x; v.y += bias[col+1] + rv.y;
                    v.z += bias[col+2] + rv.z; v.w += bias[col+3] + rv.w;
                    *(float4*)&C[oi] = v;
                } else {
                    *(float4*)&C[oi] = v;
                }
            }
        }
    }
}

extern "C" void kernel_launch(void* const* d_in, const int* in_sizes, int n_in,
                              void* d_out, int out_size) {
    const float* x    = (const float*)d_in[0];
    const float* proj = (const float*)d_in[1];
    const float* ln1g = (const float*)d_in[2];
    const float* ln1b = (const float*)d_in[3];
    const float* ln2g = (const float*)d_in[4];
    const float* ln2b = (const float*)d_in[5];
    const float* W1   = (const float*)d_in[6];
    const float* b1   = (const float*)d_in[7];
    const float* W2   = (const float*)d_in[8];
    const float* b2   = (const float*)d_in[9];
    float* out = (float*)d_out;

    cudaFuncSetAttribute(k_gemm_h<0>, cudaFuncAttributeMaxDynamicSharedMemorySize, GSMEM_BYTES);
    cudaFuncSetAttribute(k_gemm_h<1>, cudaFuncAttributeMaxDynamicSharedMemorySize, GSMEM_BYTES);
    cudaFuncSetAttribute(k_gemm_h<2>, cudaFuncAttributeMaxDynamicSharedMemorySize, GSMEM_BYTES);
    cudaFuncSetAttribute(k_gemm_h<3>, cudaFuncAttributeMaxDynamicSharedMemorySize, GSMEM_BYTES);

    __half* w1h;  cudaGetSymbolAddress((void**)&w1h,  g_w1h);
    __half* w2h;  cudaGetSymbolAddress((void**)&w2h,  g_w2h);
    __half* h2h;  cudaGetSymbolAddress((void**)&h2h,  g_h2h);
    __half* midh; cudaGetSymbolAddress((void**)&midh, g_midh);
    __half* hsh;  cudaGetSymbolAddress((void**)&hsh,  g_hsh);
    __half* prjh; cudaGetSymbolAddress((void**)&prjh, g_projh);
    __half* qph;  cudaGetSymbolAddress((void**)&qph,  g_qph);
    __half* ctxh; cudaGetSymbolAddress((void**)&ctxh, g_ctxTh);
    float* x1;    cudaGetSymbolAddress((void**)&x1,   g_x1);
    float* u;     cudaGetSymbolAddress((void**)&u,    g_u);
    float* ctxp;  cudaGetSymbolAddress((void**)&ctxp, g_ctx);

    // input-only prep
    k_transposeh<<<dim3(Fq/32, Eq/32), dim3(32,8)>>>(W1, w1h, Eq, Fq);
    k_transposeh<<<dim3(Eq/32, Fq/32), dim3(32,8)>>>(W2, w2h, Fq, Eq);
    k_roundproj<<<Mq*Dhq/256, 256>>>(proj);

    k_ln1<<<BN/8, 256>>>(x, ln1g, ln1b);
    // u = hsh @ projh^T : [98304 x 64] @ [64 x 256]
    k_gemm_h<2><<<dim3(Mq/128, ROWS/128), 256, GSMEM_BYTES>>>(hsh, Dhq, 0, prjh, Dhq, 0, nullptr, nullptr, u, nullptr, Mq);
    k_stabq_exp<<<ROWS/8, 256>>>();
    k_stabk<<<Bq*Hq, 256>>>();
    k_scale<<<ROWS/256, 256>>>();
    cudaMemsetAsync(ctxp, 0, (size_t)Bq*Hq*Mq*Dhq*sizeof(float));
    k_ksum_init<<<Bq*Hq, 256>>>();
    k_ctx<<<dim3(2, Bq*Hq, 8), 256>>>();
    k_ctxh<<<dim3(2, 8, Bq*Hq), dim3(32,8)>>>();
    k_ctxh2<<<Bq*Hq, 256>>>();
    // attn: per head [2048 x 256] @ [256 x 128(ctx^T|ksum|0)] -> x1 = x + num/den
    k_gemm_h<3><<<dim3(1, Nq/128, Bq*Hq), 256, GSMEM_BYTES>>>(
        qph, Mq, (size_t)Nq*Mq, ctxh, Mq, (size_t)128*Mq, nullptr, x, x1, nullptr, 0);
    k_ln2<<<BN/8, 256>>>(ln2g, ln2b);

    // MLP GEMM1: [8192x768]@[768x3072] -> midh (gelu, half)
    k_gemm_h<0><<<dim3(Fq/128, BN/128), 256, GSMEM_BYTES>>>(h2h, Eq, 0, w1h, Eq, 0, b1, nullptr, nullptr, midh, Fq);
    // MLP GEMM2: [8192x3072]@[3072x768] + bias + x1 -> out
    k_gemm_h<1><<<dim3(Eq/128, BN/128), 256, GSMEM_BYTES>>>(midh, Fq, 0, w2h, Fq, 0, b2, x1, out, nullptr, Eq);
}

// round 9
// speedup vs baseline: 4.8487x; 1.2986x over previous
#include <cuda_runtime.h>
#include <cuda_fp16.h>
#include <math.h>
#include <stdint.h>

// Shapes (fixed by the problem)
#define Bq 4
#define Nq 2048
#define Eq 768
#define Hq 12
#define Mq 256
#define Dhq 64
#define Fq 3072
#define ROWS (Bq*Hq*Nq)   // 98304
#define BN (Bq*Nq)        // 8192

#define RATIO 0.0625f            // M^-0.5
#define REPS  6.25e-6f           // RATIO * EPS(1e-4)
#define XSCL  0.35355339059327373f  // Dh^-0.25

// Scratch (device globals; allocation-free)
__device__ __half g_hsh[ROWS*Dhq];    // half(y*XSCL), head layout
__device__ __half g_hTh[Bq*Hq*128*Nq];// per head: [128 x 2048]: rows 0-63 hsh^T, row 64 ones, rest 0
__device__ __half g_projh[Mq*Dhq];    // half proj
__device__ float  g_u[ROWS*Mq];       // raw u (never overwritten)
__device__ __half g_qph[ROWS*Mq];     // half(e*RATIO + REPS)
__device__ __half g_kphT[ROWS*Mq];    // per head transposed: [m][n] = half(e*scale_n + REPS)
__device__ float  g_diag[ROWS];
__device__ float  g_stabq[ROWS];
__device__ float  g_scale[ROWS];      // RATIO*exp(stabq - stabk)
__device__ float  g_stabk[Bq*Hq];
__device__ __half g_ctxTh[Bq*Hq*128*Mq];  // per head [128 x 256]: d<64 ctx^T, row 64 ksum, rest 0
__device__ float  g_x1[BN*Eq];        // x + attn
__device__ __half g_h2h[BN*Eq];       // LN2 out (half)
__device__ __half g_midh[BN*Fq];      // gelu(h2@W1+b1) (half)
__device__ __half g_w1h[Fq*Eq];       // W1^T half
__device__ __half g_w2h[Eq*Fq];       // W2^T half

// ======================= helpers =======================
__device__ __forceinline__ uint32_t s2u(const void* p){
    uint32_t a;
    asm("{ .reg .u64 t; cvta.to.shared.u64 t, %1; cvt.u32.u64 %0, t; }":"=r"(a):"l"(p));
    return a;
}
__device__ __forceinline__ void cpasync16(uint32_t sa, const void* ga){
    asm volatile("cp.async.cg.shared.global [%0], [%1], 16;" :: "r"(sa), "l"(ga));
}
__device__ __forceinline__ void mma16(float* d, const uint32_t* a, const uint32_t* b){
    asm volatile("mma.sync.aligned.m16n8k16.row.col.f32.f16.f16.f32 "
        "{%0,%1,%2,%3}, {%4,%5,%6,%7}, {%8,%9}, {%0,%1,%2,%3};"
        : "+f"(d[0]),"+f"(d[1]),"+f"(d[2]),"+f"(d[3])
        : "r"(a[0]),"r"(a[1]),"r"(a[2]),"r"(a[3]),"r"(b[0]),"r"(b[1]));
}
#define LDSM4(r0,r1,r2,r3,ad) \
    asm volatile("ldmatrix.sync.aligned.m8n8.x4.shared.b16 {%0,%1,%2,%3}, [%4];" \
        : "=r"(r0),"=r"(r1),"=r"(r2),"=r"(r3) : "r"(ad))

// ---------------- LN1: warp-per-token (hsh + diag only) ----------------
__global__ void k_ln1(const float* __restrict__ x, const float* __restrict__ g,
                      const float* __restrict__ b) {
    int warp = (blockIdx.x*256 + threadIdx.x) >> 5;   // token 0..8191
    int l = threadIdx.x & 31;
    const float4* xr = (const float4*)(x + (size_t)warp*Eq);
    float4 v[6];
    float s1 = 0.f, s2 = 0.f;
    #pragma unroll
    for (int i=0;i<6;i++){
        v[i] = xr[l + 32*i];
        s1 += v[i].x+v[i].y+v[i].z+v[i].w;
        s2 += v[i].x*v[i].x+v[i].y*v[i].y+v[i].z*v[i].z+v[i].w*v[i].w;
    }
    #pragma unroll
    for (int o=16;o;o>>=1){ s1+=__shfl_xor_sync(~0u,s1,o); s2+=__shfl_xor_sync(~0u,s2,o); }
    float m = s1*(1.f/Eq);
    float rstd = rsqrtf(s2*(1.f/Eq) - m*m + 1e-5f);
    int bb = warp>>11, n = warp&2047;
    #pragma unroll
    for (int i=0;i<6;i++){
        int f = l + 32*i;
        int e = f*4;
        float4 gv = ((const float4*)g)[f];
        float4 bv = ((const float4*)b)[f];
        float4 y;
        y.x = (v[i].x-m)*rstd*gv.x + bv.x;
        y.y = (v[i].y-m)*rstd*gv.y + bv.y;
        y.z = (v[i].z-m)*rstd*gv.z + bv.z;
        y.w = (v[i].w-m)*rstd*gv.w + bv.w;
        int hd = e>>6, d = e&63;
        size_t hi = ((size_t)(bb*Hq+hd)*Nq + n)*Dhq + d;
        *(__half2*)&g_hsh[hi]   = __floats2half2_rn(y.x*XSCL, y.y*XSCL);
        *(__half2*)&g_hsh[hi+2] = __floats2half2_rn(y.z*XSCL, y.w*XSCL);
        float yy = y.x*y.x + y.y*y.y + y.z*y.z + y.w*y.w;
        #pragma unroll
        for (int o=8;o;o>>=1) yy += __shfl_xor_sync(~0u,yy,o);
        if ((l&15)==0){
            int hd2 = 2*i + (l>>4);
            g_diag[(bb*Hq+hd2)*Nq + n] = 0.0625f * yy;
        }
    }
}

// ---------------- LN2: warp-per-token, half out ----------------
__global__ void k_ln2(const float* __restrict__ g, const float* __restrict__ b) {
    int warp = (blockIdx.x*256 + threadIdx.x) >> 5;
    int l = threadIdx.x & 31;
    const float4* xr = (const float4*)(g_x1 + (size_t)warp*Eq);
    float4 v[6];
    float s1 = 0.f, s2 = 0.f;
    #pragma unroll
    for (int i=0;i<6;i++){
        v[i] = xr[l + 32*i];
        s1 += v[i].x+v[i].y+v[i].z+v[i].w;
        s2 += v[i].x*v[i].x+v[i].y*v[i].y+v[i].z*v[i].z+v[i].w*v[i].w;
    }
    #pragma unroll
    for (int o=16;o;o>>=1){ s1+=__shfl_xor_sync(~0u,s1,o); s2+=__shfl_xor_sync(~0u,s2,o); }
    float m = s1*(1.f/Eq);
    float rstd = rsqrtf(s2*(1.f/Eq) - m*m + 1e-5f);
    __half* hr = g_h2h + (size_t)warp*Eq;
    #pragma unroll
    for (int i=0;i<6;i++){
        int f = l + 32*i;
        float4 gv = ((const float4*)g)[f];
        float4 bv = ((const float4*)b)[f];
        float4 y;
        y.x = (v[i].x-m)*rstd*gv.x + bv.x;
        y.y = (v[i].y-m)*rstd*gv.y + bv.y;
        y.z = (v[i].z-m)*rstd*gv.z + bv.z;
        y.w = (v[i].w-m)*rstd*gv.w + bv.w;
        *(__half2*)&hr[f*4]   = __floats2half2_rn(y.x, y.y);
        *(__half2*)&hr[f*4+2] = __floats2half2_rn(y.z, y.w);
    }
}

__global__ void k_roundproj(const float* __restrict__ proj) {
    int i = blockIdx.x*256 + threadIdx.x;
    g_projh[i] = __float2half(proj[i]);
}

// ---------------- row max (stab_q) over raw u ----------------
__global__ void k_stabq() {
    int row = blockIdx.x*8 + (threadIdx.x>>5);
    int l = threadIdx.x & 31;
    const float* u = g_u + (size_t)row*256;
    float m = -1e30f;
    #pragma unroll
    for (int j=0;j<8;j++) m = fmaxf(m, u[l + j*32]);
    #pragma unroll
    for (int o=16;o;o>>=1) m = fmaxf(m, __shfl_xor_sync(~0u,m,o));
    if (l==0) g_stabq[row] = m;
}

// ---------------- per-head max (stab_k) ----------------
__global__ void k_stabk() {
    int g = blockIdx.x, tid = threadIdx.x;
    __shared__ float red[8];
    float m = -1e30f;
    #pragma unroll
    for (int j=0;j<8;j++) m = fmaxf(m, g_stabq[g*2048 + tid + j*256]);
    #pragma unroll
    for (int o=16;o;o>>=1) m = fmaxf(m, __shfl_xor_sync(~0u,m,o));
    if ((tid&31)==0) red[tid>>5] = m;
    __syncthreads();
    if (tid==0){
        float t = red[0];
        #pragma unroll
        for (int i=1;i<8;i++) t = fmaxf(t, red[i]);
        g_stabk[g] = t;
    }
}

__global__ void k_scale() {
    int r = blockIdx.x*256 + threadIdx.x;
    g_scale[r] = RATIO * __expf(g_stabq[r] - g_stabk[r>>11]);
}

// ---------------- qp (half) + kp^T (half, transposed) from raw u, one pass ----------------
__global__ void k_qk_exp() {
    __shared__ float t[32][33];
    int g = blockIdx.z, m0 = blockIdx.x*32, n0 = blockIdx.y*32;
    int x = threadIdx.x, y = threadIdx.y;   // block (32,8)
    #pragma unroll
    for (int i=0;i<32;i+=8){
        int n = n0 + y + i;
        size_t ro = ((size_t)g*2048 + n)*256;
        float uv = g_u[ro + m0 + x];
        float dg = g_diag[g*2048+n], sq = g_stabq[g*2048+n], sc = g_scale[g*2048+n];
        float e = __expf(uv - dg - sq);
        g_qph[ro + m0 + x] = __float2half(fmaf(e, RATIO, REPS));
        t[y+i][x] = fmaf(e, sc, REPS);            // kv at [n_loc][m_loc]
    }
    __syncthreads();
    #pragma unroll
    for (int i=0;i<32;i+=8){
        int m = m0 + y + i;
        g_kphT[((size_t)g*256 + m)*2048 + n0 + x] = __float2half(t[x][y+i]);
    }
}

// ---------------- hTh: per head [128 x 2048]: rows 0-63 = hsh^T ----------------
__global__ void k_hT() {
    __shared__ __half t[32][33];
    int g = blockIdx.z, d0 = blockIdx.x*32, n0 = blockIdx.y*32;
    int x = threadIdx.x, y = threadIdx.y;   // block (32,8)
    #pragma unroll
    for (int i=0;i<32;i+=8)
        t[y+i][x] = g_hsh[((size_t)g*2048 + n0+y+i)*64 + d0 + x];   // [n_loc][d_loc]
    __syncthreads();
    #pragma unroll
    for (int i=0;i<32;i+=8)
        g_hTh[(size_t)g*128*2048 + (size_t)(d0+y+i)*2048 + n0 + x] = t[x][y+i];
}
// rows 64..127: row 64 = ones, rest zero
__global__ void k_hT2() {
    int g = blockIdx.x, r2 = blockIdx.y;    // r2 0..63
    __half val = (r2==0) ? __float2half(1.f) : __float2half(0.f);
    __half* base = g_hTh + (size_t)g*128*2048 + (size_t)(64+r2)*2048;
    for (int c = threadIdx.x; c < 2048; c += 256) base[c] = val;
}

// ---------------- transpose weights to half ----------------
__global__ void k_transposeh(const float* __restrict__ in, __half* __restrict__ out,
                             int R, int C) {
    __shared__ float t[32][33];
    int bx = blockIdx.x*32, by = blockIdx.y*32;
    int x = threadIdx.x, y = threadIdx.y;
    #pragma unroll
    for (int i=0;i<32;i+=8)
        t[y+i][x] = in[(size_t)(by+y+i)*C + bx+x];
    __syncthreads();
    #pragma unroll
    for (int i=0;i<32;i+=8)
        out[(size_t)(bx+y+i)*R + by+x] = __float2half(t[x][y+i]);
}

// ================= f16 mma.sync GEMM (ldmatrix, 3-stage, 1 sync/iter) =================
// EPI 0: Ch=half(gelu(acc+bias)). EPI 1: C=acc+bias+resid. EPI 2: C=acc (float).
// EPI 3: attention: col 64 = denom; C = resid + num/den (head layout scatter).
// EPI 4: ctx epilogue: write g_ctxTh[z][d][m] = half(acc * (d<64 ? 1/XSCL : 1)).
#define STB 80                        // smem row stride bytes (40 halves)
#define STAGE_A 10240                 // 128 rows * 80 B
#define STAGE   (2*STAGE_A)           // 20480
#define GSMEM_BYTES (3*STAGE)         // 61440 B

template<int EPI>
__global__ __launch_bounds__(256, 2) void k_gemm_h(
        const __half* __restrict__ A, int lda, size_t strA,
        const __half* __restrict__ Bt, int Kdim, size_t strB,
        const float* __restrict__ bias,
        const float* __restrict__ resid,
        float* __restrict__ C, __half* __restrict__ Ch, int ldc) {
    extern __shared__ __align__(16) char dsm[];
    uint32_t smb = s2u(dsm);
    int tid = threadIdx.x, wid = tid>>5, lane = tid&31;
    int wm = (wid&1)*64, wn = (wid>>1)*32;
    int r = lane>>2, cq = lane&3;
    int z = blockIdx.z;

    int rbase = blockIdx.y*128, cbase = (EPI==4) ? 0 : blockIdx.x*128;
    const __half* Ag = A  + z*strA + (size_t)rbase*lda;
    const __half* Bg = Bt + z*strB + (size_t)cbase*Kdim;
    int KT = Kdim >> 5;

    uint32_t a_ldsm_base = (uint32_t)((wm + (lane&7) + ((lane>>3)&1)*8)*STB + ((lane>>4)&1)*16);
    uint32_t b_ldsm_base = (uint32_t)((wn + (lane&7) + ((lane>>4)&1)*8)*STB + ((lane>>3)&1)*16);

    float acc[4][4][4];
    #pragma unroll
    for (int i=0;i<4;i++)
        #pragma unroll
        for (int j=0;j<4;j++)
            #pragma unroll
            for (int k=0;k<4;k++) acc[i][j][k]=0.f;

    #define LOAD_STAGE(s, kt) do { \
        uint32_t _ab = smb + (uint32_t)((s)*STAGE); \
        uint32_t _bb = _ab + STAGE_A; \
        const __half* _Ag = Ag + (kt)*32; \
        const __half* _Bg = Bg + (kt)*32; \
        _Pragma("unroll") \
        for (int _t=0;_t<2;_t++){ \
            int _q = tid + _t*256; int _r = _q>>2, _c = _q&3; \
            cpasync16(_ab + (uint32_t)(_r*STB + _c*16), _Ag + (size_t)_r*lda  + _c*8); \
            cpasync16(_bb + (uint32_t)(_r*STB + _c*16), _Bg + (size_t)_r*Kdim + _c*8); \
        } \
        asm volatile("cp.async.commit_group;" ::: "memory"); \
    } while(0)

    LOAD_STAGE(0, 0);
    if (KT > 1) LOAD_STAGE(1, 1);
    int cur = 0;
    for (int kt=0; kt<KT; kt++){
        if (kt+1 < KT) asm volatile("cp.async.wait_group 1;" ::: "memory");
        else           asm volatile("cp.async.wait_group 0;" ::: "memory");
        __syncthreads();
        if (kt+2 < KT){
            int nxt = cur+2; if (nxt>=3) nxt-=3;
            LOAD_STAGE(nxt, kt+2);
        }
        uint32_t ab = smb + (uint32_t)(cur*STAGE) + a_ldsm_base;
        uint32_t bb = smb + (uint32_t)(cur*STAGE) + STAGE_A + b_ldsm_base;
        #pragma unroll
        for (int ks=0; ks<2; ks++){
            uint32_t a[4][4], b[2][4];
            #pragma unroll
            for (int mf=0; mf<4; mf++)
                LDSM4(a[mf][0],a[mf][1],a[mf][2],a[mf][3], ab + mf*16*STB + ks*32);
            #pragma unroll
            for (int p=0; p<2; p++)
                LDSM4(b[p][0],b[p][1],b[p][2],b[p][3], bb + p*16*STB + ks*32);
            #pragma unroll
            for (int mf=0; mf<4; mf++)
                #pragma unroll
                for (int nf=0; nf<4; nf++)
                    mma16(acc[mf][nf], a[mf], &b[nf>>1][(nf&1)*2]);
        }
        cur = (cur==2) ? 0 : cur+1;
    }
    #undef LOAD_STAGE

    // Epilogue: two 64-row halves staged through smem (stride 132)
    float* stg = (float*)dsm;
    #pragma unroll 1
    for (int h=0; h<2; h++){
        __syncthreads();
        if ((wid&1) == h){
            #pragma unroll
            for (int mf=0; mf<4; mf++)
                #pragma unroll
                for (int nf=0; nf<4; nf++){
                    int row = mf*16 + r, col = wn + nf*8 + 2*cq;
                    *(float2*)&stg[row*132 + col]     = make_float2(acc[mf][nf][0], acc[mf][nf][1]);
                    *(float2*)&stg[(row+8)*132 + col] = make_float2(acc[mf][nf][2], acc[mf][nf][3]);
                }
        }
        __syncthreads();
        if (EPI == 4){
            #pragma unroll
            for (int t=0;t<32;t++){
                int q = tid + t*256;          // 0..8191
                int d = q>>6;                 // 0..127
                int ml = q&63;                // 0..63
                float v = stg[ml*132 + d];
                if (d < 64) v *= (1.0f/XSCL);
                g_ctxTh[(size_t)z*128*256 + d*256 + (rbase + h*64 + ml)] = __float2half(v);
            }
        } else {
            #pragma unroll
            for (int t=0;t<8;t++){
                int q = tid + t*256; int row = q>>5, c4 = (q&31)*4;
                int col = cbase + c4;
                if (EPI == 3){
                    if (c4 < 64){
                        float4 v = *(const float4*)&stg[row*132 + c4];
                        float dinv = 1.f / stg[row*132 + 64];
                        int bb2 = z/12, hd = z%12;
                        int n = rbase + h*64 + row;
                        size_t oi = ((size_t)(bb2*2048 + n))*768 + hd*64 + c4;
                        float4 rv = *(const float4*)&resid[oi];
                        v.x = rv.x + v.x*dinv; v.y = rv.y + v.y*dinv;
                        v.z = rv.z + v.z*dinv; v.w = rv.w + v.w*dinv;
                        *(float4*)&C[oi] = v;
                    }
                } else {
                    float4 v = *(const float4*)&stg[row*132 + c4];
                    size_t oi = (size_t)(rbase + h*64 + row)*ldc + col;
                    if (EPI == 0){
                        v.x += bias[col+0]; v.y += bias[col+1]; v.z += bias[col+2]; v.w += bias[col+3];
                        v.x = 0.5f*v.x*(1.f+erff(v.x*0.70710678118654752f));
                        v.y = 0.5f*v.y*(1.f+erff(v.y*0.70710678118654752f));
                        v.z = 0.5f*v.z*(1.f+erff(v.z*0.70710678118654752f));
                        v.w = 0.5f*v.w*(1.f+erff(v.w*0.70710678118654752f));
                        *reinterpret_cast<__half2*>(Ch + oi)     = __floats2half2_rn(v.x, v.y);
                        *reinterpret_cast<__half2*>(Ch + oi + 2) = __floats2half2_rn(v.z, v.w);
                    } else if (EPI == 1){
                        float4 rv = *(const float4*)&resid[oi];
                        v.x += bias[col+0] + rv.x; v.y += bias[col+1] + rv.y;
                        v.z += bias[col+2] + rv.z; v.w += bias[col+3] + rv.w;
                        *(float4*)&C[oi] = v;
                    } else {
                        *(float4*)&C[oi] = v;
                    }
                }
            }
        }
    }
}

extern "C" void kernel_launch(void* const* d_in, const int* in_sizes, int n_in,
                              void* d_out, int out_size) {
    const float* x    = (const float*)d_in[0];
    const float* proj = (const float*)d_in[1];
    const float* ln1g = (const float*)d_in[2];
    const float* ln1b = (const float*)d_in[3];
    const float* ln2g = (const float*)d_in[4];
    const float* ln2b = (const float*)d_in[5];
    const float* W1   = (const float*)d_in[6];
    const float* b1   = (const float*)d_in[7];
    const float* W2   = (const float*)d_in[8];
    const float* b2   = (const float*)d_in[9];
    float* out = (float*)d_out;

    cudaFuncSetAttribute(k_gemm_h<0>, cudaFuncAttributeMaxDynamicSharedMemorySize, GSMEM_BYTES);
    cudaFuncSetAttribute(k_gemm_h<1>, cudaFuncAttributeMaxDynamicSharedMemorySize, GSMEM_BYTES);
    cudaFuncSetAttribute(k_gemm_h<2>, cudaFuncAttributeMaxDynamicSharedMemorySize, GSMEM_BYTES);
    cudaFuncSetAttribute(k_gemm_h<3>, cudaFuncAttributeMaxDynamicSharedMemorySize, GSMEM_BYTES);
    cudaFuncSetAttribute(k_gemm_h<4>, cudaFuncAttributeMaxDynamicSharedMemorySize, GSMEM_BYTES);

    __half* w1h;  cudaGetSymbolAddress((void**)&w1h,  g_w1h);
    __half* w2h;  cudaGetSymbolAddress((void**)&w2h,  g_w2h);
    __half* h2h;  cudaGetSymbolAddress((void**)&h2h,  g_h2h);
    __half* midh; cudaGetSymbolAddress((void**)&midh, g_midh);
    __half* hsh;  cudaGetSymbolAddress((void**)&hsh,  g_hsh);
    __half* prjh; cudaGetSymbolAddress((void**)&prjh, g_projh);
    __half* qph;  cudaGetSymbolAddress((void**)&qph,  g_qph);
    __half* kpht; cudaGetSymbolAddress((void**)&kpht, g_kphT);
    __half* hth;  cudaGetSymbolAddress((void**)&hth,  g_hTh);
    __half* ctxh; cudaGetSymbolAddress((void**)&ctxh, g_ctxTh);
    float* x1;    cudaGetSymbolAddress((void**)&x1,   g_x1);
    float* u;     cudaGetSymbolAddress((void**)&u,    g_u);

    // input-only prep
    k_transposeh<<<dim3(Fq/32, Eq/32), dim3(32,8)>>>(W1, w1h, Eq, Fq);
    k_transposeh<<<dim3(Eq/32, Fq/32), dim3(32,8)>>>(W2, w2h, Fq, Eq);
    k_roundproj<<<Mq*Dhq/256, 256>>>(proj);

    k_ln1<<<BN/8, 256>>>(x, ln1g, ln1b);
    // u = hsh @ projh^T : [98304 x 64] @ [64 x 256]
    k_gemm_h<2><<<dim3(Mq/128, ROWS/128), 256, GSMEM_BYTES>>>(hsh, Dhq, 0, prjh, Dhq, 0, nullptr, nullptr, u, nullptr, Mq);
    k_stabq<<<ROWS/8, 256>>>();
    k_stabk<<<Bq*Hq, 256>>>();
    k_scale<<<ROWS/256, 256>>>();
    k_qk_exp<<<dim3(Mq/32, Nq/32, Bq*Hq), dim3(32,8)>>>();
    k_hT<<<dim3(2, Nq/32, Bq*Hq), dim3(32,8)>>>();
    k_hT2<<<dim3(Bq*Hq, 64), 256>>>();
    // ctx GEMM: per head [256 x 2048] @ [2048 x 128(hT|1|0)] -> ctxTh (transposed epilogue)
    k_gemm_h<4><<<dim3(1, 2, Bq*Hq), 256, GSMEM_BYTES>>>(
        kpht, Nq, (size_t)Mq*Nq, hth, Nq, (size_t)128*Nq, nullptr, nullptr, nullptr, nullptr, 0);
    // attn: per head [2048 x 256] @ [256 x 128(ctx^T|ksum|0)] -> x1 = x + num/den
    k_gemm_h<3><<<dim3(1, Nq/128, Bq*Hq), 256, GSMEM_BYTES>>>(
        qph, Mq, (size_t)Nq*Mq, ctxh, Mq, (size_t)128*Mq, nullptr, x, x1, nullptr, 0);
    k_ln2<<<BN/8, 256>>>(ln2g, ln2b);

    // MLP GEMM1: [8192x768]@[768x3072] -> midh (gelu, half)
    k_gemm_h<0><<<dim3(Fq/128, BN/128), 256, GSMEM_BYTES>>>(h2h, Eq, 0, w1h, Eq, 0, b1, nullptr, nullptr, midh, Fq);
    // MLP GEMM2: [8192x3072]@[3072x768] + bias + x1 -> out
    k_gemm_h<1><<<dim3(Eq/128, BN/128), 256, GSMEM_BYTES>>>(midh, Fq, 0, w2h, Fq, 0, b2, x1, out, nullptr, Eq);
}